// round 6
// baseline (speedup 1.0000x reference)
#include <cuda_runtime.h>
#include <cuda_bf16.h>
#include <cfloat>
#include <cstdint>

#define B_ 2
#define N_ 2048
#define C_ 1024
#define H_ 16
#define D_ 64

typedef __nv_bfloat16 bf16;

// ---------------------------------------------------------------------------
// Scratch (allocation-free rule: __device__ globals)
// ---------------------------------------------------------------------------
__device__ float g_v[B_ * H_ * N_ * D_];
__device__ bf16 g_qhi[B_ * H_ * N_ * D_], g_qlo[B_ * H_ * N_ * D_];
__device__ bf16 g_khi[B_ * H_ * N_ * D_], g_klo[B_ * H_ * N_ * D_];
__device__ bf16 g_vthi[B_ * H_ * D_ * N_], g_vtlo[B_ * H_ * D_ * N_];
__device__ bf16 g_xhi[B_ * N_ * C_], g_xlo[B_ * N_ * C_];
__device__ bf16 g_wqkvhi[3 * C_ * C_], g_wqkvlo[3 * C_ * C_];
__device__ bf16 g_wprojhi[C_ * C_], g_wprojlo[C_ * C_];
__device__ bf16 g_atthi[B_ * N_ * C_], g_attlo[B_ * N_ * C_];

// ---------------------------------------------------------------------------
// Family-agnostic PTX helpers
// ---------------------------------------------------------------------------
__device__ __forceinline__ uint32_t smem_u32(const void* p) {
    uint32_t a;
    asm("{ .reg .u64 t; cvta.to.shared.u64 t, %1; cvt.u32.u64 %0, t; }" : "=r"(a) : "l"(p));
    return a;
}
#define CP16(saddr, gptr) \
    asm volatile("cp.async.cg.shared.global [%0], [%1], 16;" ::"r"(saddr), "l"(gptr) : "memory")
#define CP_COMMIT() asm volatile("cp.async.commit_group;" ::: "memory")
#define CP_WAIT0()  asm volatile("cp.async.wait_group 0;" ::: "memory")

#define LDSM4(R0, R1, R2, R3, A)                                             \
    asm volatile("ldmatrix.sync.aligned.m8n8.x4.shared.b16 {%0,%1,%2,%3}, [%4];" \
                 : "=r"(R0), "=r"(R1), "=r"(R2), "=r"(R3) : "r"(A))

__device__ __forceinline__ void mma_bf16(float c[4], uint32_t a0, uint32_t a1, uint32_t a2,
                                         uint32_t a3, uint32_t b0, uint32_t b1) {
    asm volatile(
        "mma.sync.aligned.m16n8k16.row.col.f32.bf16.bf16.f32 "
        "{%0,%1,%2,%3},{%4,%5,%6,%7},{%8,%9},{%0,%1,%2,%3};"
        : "+f"(c[0]), "+f"(c[1]), "+f"(c[2]), "+f"(c[3])
        : "r"(a0), "r"(a1), "r"(a2), "r"(a3), "r"(b0), "r"(b1));
}

__device__ __forceinline__ uint32_t pack_bf16(bf16 lo, bf16 hi) {
    __nv_bfloat162 t; t.x = lo; t.y = hi;
    return *(uint32_t*)&t;
}
__device__ __forceinline__ void split2(float x, float y, uint32_t& hp, uint32_t& lp) {
    bf16 hx = __float2bfloat16_rn(x), hy = __float2bfloat16_rn(y);
    float lx = x - __bfloat162float(hx), ly = y - __bfloat162float(hy);
    hp = pack_bf16(hx, hy);
    lp = pack_bf16(__float2bfloat16_rn(lx), __float2bfloat16_rn(ly));
}

// ---------------------------------------------------------------------------
// 128x128x1024 split-bf16 (3-pass) mma.sync mainloop with ldmatrix fragments.
// ---------------------------------------------------------------------------
#define PITCH 40
#define CH (128 * PITCH)
#define CHB (CH * 2)
#define SMEM_GEMM (1024 + 8 * CHB)

__device__ __forceinline__ void gemm_ml(float acc[4][4][4],
                                        const bf16* __restrict__ Ahi,
                                        const bf16* __restrict__ Alo,
                                        const bf16* __restrict__ Bhi,
                                        const bf16* __restrict__ Blo,
                                        int m0, int n0, bf16* sa) {
    const int tid = threadIdx.x;
    const int wid = tid >> 5, lane = tid & 31;
    const int wm = wid & 1, wn = wid >> 1;
    const int grow = tid >> 1, gcol = (tid & 1) * 16;

    const uint32_t sab = smem_u32(sa);
    const uint32_t so = (uint32_t)(grow * PITCH + gcol) * 2;

    // ldmatrix lane-relative byte offsets
    const uint32_t la = ((uint32_t)(lane & 15) * PITCH + (uint32_t)(lane >> 4) * 8) * 2;
    const uint32_t lb = ((uint32_t)((lane & 7) + ((lane >> 4) << 3)) * PITCH +
                        (uint32_t)((lane >> 3) & 1) * 8) * 2;

    const bf16* pAh = Ahi + (size_t)(m0 + grow) * C_ + gcol;
    const bf16* pAl = Alo + (size_t)(m0 + grow) * C_ + gcol;
    const bf16* pBh = Bhi + (size_t)(n0 + grow) * C_ + gcol;
    const bf16* pBl = Blo + (size_t)(n0 + grow) * C_ + gcol;

    {
        CP16(sab + 0 * CHB + so,      pAh);
        CP16(sab + 0 * CHB + so + 16, pAh + 8);
        CP16(sab + 2 * CHB + so,      pAl);
        CP16(sab + 2 * CHB + so + 16, pAl + 8);
        CP16(sab + 4 * CHB + so,      pBh);
        CP16(sab + 4 * CHB + so + 16, pBh + 8);
        CP16(sab + 6 * CHB + so,      pBl);
        CP16(sab + 6 * CHB + so + 16, pBl + 8);
        CP_COMMIT();
        CP_WAIT0();
    }
    __syncthreads();

    for (int c = 0; c < 32; c++) {
        if (c < 31) {
            const int k0 = (c + 1) * 32;
            const uint32_t nb = (uint32_t)((c + 1) & 1) * CHB;
            CP16(sab + 0 * CHB + nb + so,      pAh + k0);
            CP16(sab + 0 * CHB + nb + so + 16, pAh + k0 + 8);
            CP16(sab + 2 * CHB + nb + so,      pAl + k0);
            CP16(sab + 2 * CHB + nb + so + 16, pAl + k0 + 8);
            CP16(sab + 4 * CHB + nb + so,      pBh + k0);
            CP16(sab + 4 * CHB + nb + so + 16, pBh + k0 + 8);
            CP16(sab + 6 * CHB + nb + so,      pBl + k0);
            CP16(sab + 6 * CHB + nb + so + 16, pBl + k0 + 8);
            CP_COMMIT();
        }
        const uint32_t bob = (uint32_t)(c & 1) * CHB;
        const uint32_t ahb = sab + bob;
        const uint32_t alb = sab + 2 * CHB + bob;
        const uint32_t bhb = sab + 4 * CHB + bob;
        const uint32_t blb = sab + 6 * CHB + bob;
#pragma unroll
        for (int kf = 0; kf < 2; kf++) {
            const uint32_t kfo = (uint32_t)kf * 32;  // 16 halves
            uint32_t afh[4][4], afl[4][4];
#pragma unroll
            for (int mf = 0; mf < 4; mf++) {
                const uint32_t ro = (uint32_t)((wm * 64 + mf * 16) * PITCH) * 2 + kfo;
                LDSM4(afh[mf][0], afh[mf][1], afh[mf][2], afh[mf][3], ahb + ro + la);
                LDSM4(afl[mf][0], afl[mf][1], afl[mf][2], afl[mf][3], alb + ro + la);
            }
            uint32_t bfh[4][2], bfl[4][2];
#pragma unroll
            for (int np = 0; np < 2; np++) {
                const uint32_t ro = (uint32_t)((wn * 32 + np * 16) * PITCH) * 2 + kfo;
                LDSM4(bfh[2 * np][0], bfh[2 * np][1], bfh[2 * np + 1][0], bfh[2 * np + 1][1],
                      bhb + ro + lb);
                LDSM4(bfl[2 * np][0], bfl[2 * np][1], bfl[2 * np + 1][0], bfl[2 * np + 1][1],
                      blb + ro + lb);
            }
#pragma unroll
            for (int mf = 0; mf < 4; mf++)
#pragma unroll
                for (int nf = 0; nf < 4; nf++) {
                    mma_bf16(acc[mf][nf], afh[mf][0], afh[mf][1], afh[mf][2], afh[mf][3],
                             bfh[nf][0], bfh[nf][1]);
                    mma_bf16(acc[mf][nf], afh[mf][0], afh[mf][1], afh[mf][2], afh[mf][3],
                             bfl[nf][0], bfl[nf][1]);
                    mma_bf16(acc[mf][nf], afl[mf][0], afl[mf][1], afl[mf][2], afl[mf][3],
                             bfh[nf][0], bfh[nf][1]);
                }
        }
        if (c < 31) CP_WAIT0();
        __syncthreads();
    }
}

// ---------------------------------------------------------------------------
// fp32 -> (hi, lo) bf16 split
// ---------------------------------------------------------------------------
__global__ __launch_bounds__(256) void conv_kernel(const float* __restrict__ src,
                                                   int sel, int n4) {
    bf16* hi = (sel == 0) ? g_xhi : (sel == 1) ? g_wqkvhi : g_wprojhi;
    bf16* lo = (sel == 0) ? g_xlo : (sel == 1) ? g_wqkvlo : g_wprojlo;
    int i = blockIdx.x * 256 + threadIdx.x;
    if (i >= n4) return;
    float4 v = ((const float4*)src)[i];
    uint32_t hp[2], lp[2];
    split2(v.x, v.y, hp[0], lp[0]);
    split2(v.z, v.w, hp[1], lp[1]);
    *(uint32_t*)(hi + 4 * (size_t)i)     = hp[0];
    *(uint32_t*)(hi + 4 * (size_t)i + 2) = hp[1];
    *(uint32_t*)(lo + 4 * (size_t)i)     = lp[0];
    *(uint32_t*)(lo + 4 * (size_t)i + 2) = lp[1];
}

// ---------------------------------------------------------------------------
// QKV GEMM + fused per-head LayerNorm; Q,K out as bf16 hi/lo; V out fp32.
// ---------------------------------------------------------------------------
#define DPITCH 132

__global__ __launch_bounds__(256) void qkv_mma_kernel(const float* __restrict__ qg,
                                                      const float* __restrict__ qb,
                                                      const float* __restrict__ kg,
                                                      const float* __restrict__ kb) {
    extern __shared__ char smc[];
    float* sgam = (float*)smc;
    float* sbet = (float*)(smc + 256);
    bf16* sa = (bf16*)(smc + 1024);

    const int n0 = blockIdx.x * 128, m0 = blockIdx.y * 128;
    const int s = n0 >> 10;
    if (threadIdx.x < 64 && s < 2) {
        const float* gg = (s == 0) ? qg : kg;
        const float* bb = (s == 0) ? qb : kb;
        sgam[threadIdx.x] = gg[threadIdx.x];
        sbet[threadIdx.x] = bb[threadIdx.x];
    }

    float acc[4][4][4];
#pragma unroll
    for (int a = 0; a < 4; a++)
#pragma unroll
        for (int b = 0; b < 4; b++)
#pragma unroll
            for (int cc = 0; cc < 4; cc++) acc[a][b][cc] = 0.f;

    gemm_ml(acc, g_xhi, g_xlo, g_wqkvhi, g_wqkvlo, m0, n0, sa);

    float* Dst = (float*)(smc + 1024);
    const int wid = threadIdx.x >> 5, lane = threadIdx.x & 31;
    const int wm = wid & 1, wn = wid >> 1;
    const int r = lane >> 2, c4 = lane & 3;
#pragma unroll
    for (int mf = 0; mf < 4; mf++)
#pragma unroll
        for (int nf = 0; nf < 4; nf++) {
            const int m = wm * 64 + mf * 16 + r;
            const int n = wn * 32 + nf * 8 + c4 * 2;
            *(float2*)&Dst[m * DPITCH + n]       = make_float2(acc[mf][nf][0], acc[mf][nf][1]);
            *(float2*)&Dst[(m + 8) * DPITCH + n] = make_float2(acc[mf][nf][2], acc[mf][nf][3]);
        }
    __syncthreads();

    const int m = threadIdx.x >> 1, hc = threadIdx.x & 1;
    const float* rowp = Dst + m * DPITCH + hc * 64;
    float f[64];
#pragma unroll
    for (int i = 0; i < 64; i++) f[i] = rowp[i];
    const int bidx = m0 >> 11, nq = (m0 & 2047) + m;
    const int h = ((n0 & 1023) >> 6) + hc;
    const size_t base = (((size_t)(bidx * H_ + h)) * N_ + nq) * D_;
    if (s < 2) {
        float sum = 0.f;
#pragma unroll
        for (int i = 0; i < 64; i++) sum += f[i];
        float mu = sum * (1.0f / 64.0f);
        float vs = 0.f;
#pragma unroll
        for (int i = 0; i < 64; i++) { float d = f[i] - mu; vs += d * d; }
        float rs = rsqrtf(vs * (1.0f / 64.0f) + 1e-5f);
#pragma unroll
        for (int i = 0; i < 64; i++) f[i] = (f[i] - mu) * rs * sgam[i] + sbet[i];
        bf16* dh = (s == 0) ? g_qhi : g_khi;
        bf16* dl = (s == 0) ? g_qlo : g_klo;
#pragma unroll
        for (int i = 0; i < 64; i += 2) {
            uint32_t hp, lp;
            split2(f[i], f[i + 1], hp, lp);
            *(uint32_t*)(dh + base + i) = hp;
            *(uint32_t*)(dl + base + i) = lp;
        }
    } else {
#pragma unroll
        for (int i = 0; i < 64; i += 4)
            *(float4*)&g_v[base + i] = make_float4(f[i], f[i + 1], f[i + 2], f[i + 3]);
    }
}

// ---------------------------------------------------------------------------
// V transpose + split:  g_v[b,h,key,d] -> g_vthi/lo[b,h,d,key]
// ---------------------------------------------------------------------------
__global__ __launch_bounds__(256) void vt_kernel() {
    __shared__ float tile[64][65];
    const int kt = blockIdx.x, bh = blockIdx.y;
    const int tid = threadIdx.x;
    const float* src = g_v + (size_t)bh * N_ * D_ + (size_t)(kt * 64) * D_;
#pragma unroll
    for (int j = 0; j < 4; j++) {
        int id = tid + j * 256;
        int row = id >> 4, c4i = (id & 15) * 4;
        float4 v = *(const float4*)(src + row * D_ + c4i);
        tile[row][c4i] = v.x; tile[row][c4i + 1] = v.y;
        tile[row][c4i + 2] = v.z; tile[row][c4i + 3] = v.w;
    }
    __syncthreads();
    const int d = tid >> 2, kg = (tid & 3) * 16;
    bf16* dh = g_vthi + (size_t)bh * D_ * N_ + (size_t)d * N_ + kt * 64 + kg;
    bf16* dl = g_vtlo + (size_t)bh * D_ * N_ + (size_t)d * N_ + kt * 64 + kg;
#pragma unroll
    for (int i = 0; i < 16; i += 2) {
        uint32_t hp, lp;
        split2(tile[kg + i][d], tile[kg + i + 1][d], hp, lp);
        *(uint32_t*)(dh + i) = hp;
        *(uint32_t*)(dl + i) = lp;
    }
}

// ---------------------------------------------------------------------------
// Flash attention on mma.sync (split-bf16, ldmatrix fragments).
// CTA: 128 q-rows, 8 warps (16 rows each), Bc = 64 keys/iter.
// ---------------------------------------------------------------------------
#define FP 72
#define KTILE (64 * FP)
#define SMEM_FLASH (8 * KTILE * 2)

__global__ __launch_bounds__(256) void flash_mma_kernel(const unsigned char* __restrict__ mask) {
    extern __shared__ char smc[];
    bf16* sh = (bf16*)smc;
    const uint32_t shb = smem_u32(sh);

    const int qt = blockIdx.x, h = blockIdx.y, b = blockIdx.z;
    const int tid = threadIdx.x, wid = tid >> 5, lane = tid & 31;
    const int r = lane >> 2, c4 = lane & 3;
    const int wrow = wid * 16;
    const size_t qkoff = ((size_t)(b * H_ + h)) * N_ * D_;
    const size_t vtoff = ((size_t)(b * H_ + h)) * D_ * N_;

    // ldmatrix lane-relative byte offsets (pitch FP)
    const uint32_t laf = ((uint32_t)(lane & 15) * FP + (uint32_t)(lane >> 4) * 8) * 2;
    const uint32_t lbf = ((uint32_t)((lane & 7) + ((lane >> 4) << 3)) * FP +
                         (uint32_t)((lane >> 3) & 1) * 8) * 2;

    // ---- stage Q tile and read fragments via ldmatrix ----
    {
        const bf16* qh = g_qhi + qkoff + (size_t)(qt * 128) * D_;
        const bf16* ql = g_qlo + qkoff + (size_t)(qt * 128) * D_;
#pragma unroll
        for (int j = 0; j < 4; j++) {
            int id = tid + j * 256;
            int row = id >> 3, c8 = (id & 7) * 8;
            CP16(shb + (row * FP + c8) * 2, qh + row * D_ + c8);
            CP16(shb + (2 * KTILE + row * FP + c8) * 2, ql + row * D_ + c8);
        }
        CP_COMMIT(); CP_WAIT0();
    }
    __syncthreads();

    uint32_t aQh[4][4], aQl[4][4];
#pragma unroll
    for (int kc = 0; kc < 4; kc++) {
        const uint32_t ro = (uint32_t)(wrow * FP) * 2 + (uint32_t)kc * 32;
        LDSM4(aQh[kc][0], aQh[kc][1], aQh[kc][2], aQh[kc][3], shb + ro + laf);
        LDSM4(aQl[kc][0], aQl[kc][1], aQl[kc][2], aQl[kc][3],
              shb + (uint32_t)(2 * KTILE) * 2 + ro + laf);
    }
    __syncthreads();

    float of[8][4];
#pragma unroll
    for (int nb = 0; nb < 8; nb++)
#pragma unroll
        for (int k = 0; k < 4; k++) of[nb][k] = 0.f;
    float mI0 = -FLT_MAX, mI1 = -FLT_MAX, l0 = 0.f, l1 = 0.f;

    auto issue_tile = [&](int kt2, int buf) {
        const uint32_t bo = (uint32_t)buf * 4 * KTILE * 2;
        const bf16* kh = g_khi + qkoff + (size_t)(kt2 * 64) * D_;
        const bf16* kl = g_klo + qkoff + (size_t)(kt2 * 64) * D_;
        const bf16* vh = g_vthi + vtoff + kt2 * 64;
        const bf16* vl = g_vtlo + vtoff + kt2 * 64;
#pragma unroll
        for (int j = 0; j < 2; j++) {
            int id = tid + j * 256;
            int row = id >> 3, c8 = (id & 7) * 8;
            uint32_t sd = bo + (row * FP + c8) * 2;
            CP16(shb + sd, kh + row * D_ + c8);
            CP16(shb + sd + KTILE * 2, kl + row * D_ + c8);
            CP16(shb + sd + 2 * KTILE * 2, vh + (size_t)row * N_ + c8);
            CP16(shb + sd + 3 * KTILE * 2, vl + (size_t)row * N_ + c8);
        }
        CP_COMMIT();
    };

    issue_tile(0, 0);
    CP_WAIT0();
    __syncthreads();

    const unsigned char* mb0 = mask + ((size_t)b * N_ + qt * 128 + wrow + r) * N_;
    const float scale = 0.125f;

    for (int kt2 = 0; kt2 < N_ / 64; kt2++) {
        if (kt2 < N_ / 64 - 1) issue_tile(kt2 + 1, (kt2 + 1) & 1);

        const uint32_t tb  = shb + (uint32_t)((kt2 & 1) * 4) * KTILE * 2;
        const uint32_t khb = tb;
        const uint32_t klb = tb + KTILE * 2;
        const uint32_t vhb = tb + 2 * KTILE * 2;
        const uint32_t vlb = tb + 3 * KTILE * 2;

        // ---- S = Q K^T (3-pass, ldmatrix K frags) ----
        float sf[8][4];
#pragma unroll
        for (int nb = 0; nb < 8; nb++)
            sf[nb][0] = sf[nb][1] = sf[nb][2] = sf[nb][3] = 0.f;

#pragma unroll
        for (int kc = 0; kc < 4; kc++) {
            const uint32_t kco = (uint32_t)kc * 32;
#pragma unroll
            for (int p = 0; p < 4; p++) {
                const uint32_t ro = (uint32_t)(p * 16 * FP) * 2 + kco + lbf;
                uint32_t h0, h1, h2, h3, e0, e1, e2, e3;
                LDSM4(h0, h1, h2, h3, khb + ro);
                LDSM4(e0, e1, e2, e3, klb + ro);
                mma_bf16(sf[2 * p], aQh[kc][0], aQh[kc][1], aQh[kc][2], aQh[kc][3], h0, h1);
                mma_bf16(sf[2 * p], aQh[kc][0], aQh[kc][1], aQh[kc][2], aQh[kc][3], e0, e1);
                mma_bf16(sf[2 * p], aQl[kc][0], aQl[kc][1], aQl[kc][2], aQl[kc][3], h0, h1);
                mma_bf16(sf[2 * p + 1], aQh[kc][0], aQh[kc][1], aQh[kc][2], aQh[kc][3], h2, h3);
                mma_bf16(sf[2 * p + 1], aQh[kc][0], aQh[kc][1], aQh[kc][2], aQh[kc][3], e2, e3);
                mma_bf16(sf[2 * p + 1], aQl[kc][0], aQl[kc][1], aQl[kc][2], aQl[kc][3], h2, h3);
            }
        }

        // ---- scale + mask ----
        const unsigned char* mr0 = mb0 + kt2 * 64 + c4 * 2;
#pragma unroll
        for (int nb = 0; nb < 8; nb++) {
            uchar2 k0 = *(const uchar2*)(mr0 + nb * 8);
            uchar2 k8 = *(const uchar2*)(mr0 + 8 * N_ + nb * 8);
            sf[nb][0] = k0.x ? -FLT_MAX : sf[nb][0] * scale;
            sf[nb][1] = k0.y ? -FLT_MAX : sf[nb][1] * scale;
            sf[nb][2] = k8.x ? -FLT_MAX : sf[nb][2] * scale;
            sf[nb][3] = k8.y ? -FLT_MAX : sf[nb][3] * scale;
        }

        // ---- online softmax ----
        float mx0 = -FLT_MAX, mx1 = -FLT_MAX;
#pragma unroll
        for (int nb = 0; nb < 8; nb++) {
            mx0 = fmaxf(mx0, fmaxf(sf[nb][0], sf[nb][1]));
            mx1 = fmaxf(mx1, fmaxf(sf[nb][2], sf[nb][3]));
        }
        mx0 = fmaxf(mx0, __shfl_xor_sync(0xffffffffu, mx0, 1));
        mx0 = fmaxf(mx0, __shfl_xor_sync(0xffffffffu, mx0, 2));
        mx1 = fmaxf(mx1, __shfl_xor_sync(0xffffffffu, mx1, 1));
        mx1 = fmaxf(mx1, __shfl_xor_sync(0xffffffffu, mx1, 2));
        const float mn0 = fmaxf(mI0, mx0), mn1 = fmaxf(mI1, mx1);
        const float cor0 = __expf(mI0 - mn0), cor1 = __expf(mI1 - mn1);
        mI0 = mn0; mI1 = mn1;
        float rs0 = 0.f, rs1 = 0.f;
#pragma unroll
        for (int nb = 0; nb < 8; nb++) {
            sf[nb][0] = __expf(sf[nb][0] - mn0);
            sf[nb][1] = __expf(sf[nb][1] - mn0);
            sf[nb][2] = __expf(sf[nb][2] - mn1);
            sf[nb][3] = __expf(sf[nb][3] - mn1);
            rs0 += sf[nb][0] + sf[nb][1];
            rs1 += sf[nb][2] + sf[nb][3];
        }
        rs0 += __shfl_xor_sync(0xffffffffu, rs0, 1);
        rs0 += __shfl_xor_sync(0xffffffffu, rs0, 2);
        rs1 += __shfl_xor_sync(0xffffffffu, rs1, 1);
        rs1 += __shfl_xor_sync(0xffffffffu, rs1, 2);
        l0 = l0 * cor0 + rs0;
        l1 = l1 * cor1 + rs1;
#pragma unroll
        for (int nb = 0; nb < 8; nb++) {
            of[nb][0] *= cor0; of[nb][1] *= cor0;
            of[nb][2] *= cor1; of[nb][3] *= cor1;
        }

        // ---- O += P V (3-pass, ldmatrix V frags) ----
#pragma unroll
        for (int kc = 0; kc < 4; kc++) {
            uint32_t ah[4], al[4];
            split2(sf[2 * kc][0], sf[2 * kc][1], ah[0], al[0]);
            split2(sf[2 * kc][2], sf[2 * kc][3], ah[1], al[1]);
            split2(sf[2 * kc + 1][0], sf[2 * kc + 1][1], ah[2], al[2]);
            split2(sf[2 * kc + 1][2], sf[2 * kc + 1][3], ah[3], al[3]);
            const uint32_t kco = (uint32_t)kc * 32;
#pragma unroll
            for (int p = 0; p < 4; p++) {
                const uint32_t ro = (uint32_t)(p * 16 * FP) * 2 + kco + lbf;
                uint32_t v0, v1, v2, v3, w0, w1, w2, w3;
                LDSM4(v0, v1, v2, v3, vhb + ro);
                LDSM4(w0, w1, w2, w3, vlb + ro);
                mma_bf16(of[2 * p], ah[0], ah[1], ah[2], ah[3], v0, v1);
                mma_bf16(of[2 * p], ah[0], ah[1], ah[2], ah[3], w0, w1);
                mma_bf16(of[2 * p], al[0], al[1], al[2], al[3], v0, v1);
                mma_bf16(of[2 * p + 1], ah[0], ah[1], ah[2], ah[3], v2, v3);
                mma_bf16(of[2 * p + 1], ah[0], ah[1], ah[2], ah[3], w2, w3);
                mma_bf16(of[2 * p + 1], al[0], al[1], al[2], al[3], v2, v3);
            }
        }

        if (kt2 < N_ / 64 - 1) CP_WAIT0();
        __syncthreads();
    }

    // ---- epilogue ----
    const float inv0 = 1.0f / l0, inv1 = 1.0f / l1;
    const int row0 = qt * 128 + wrow + r;
    const size_t ob0 = ((size_t)b * N_ + row0) * C_ + h * 64 + c4 * 2;
    const size_t ob1 = ob0 + 8 * (size_t)C_;
#pragma unroll
    for (int nb = 0; nb < 8; nb++) {
        uint32_t hp, lp;
        split2(of[nb][0] * inv0, of[nb][1] * inv0, hp, lp);
        *(uint32_t*)(g_atthi + ob0 + nb * 8) = hp;
        *(uint32_t*)(g_attlo + ob0 + nb * 8) = lp;
        split2(of[nb][2] * inv1, of[nb][3] * inv1, hp, lp);
        *(uint32_t*)(g_atthi + ob1 + nb * 8) = hp;
        *(uint32_t*)(g_attlo + ob1 + nb * 8) = lp;
    }
}

// ---------------------------------------------------------------------------
// Projection GEMM + bias
// ---------------------------------------------------------------------------
__global__ __launch_bounds__(256) void proj_mma_kernel(const float* __restrict__ bias,
                                                       float* __restrict__ out) {
    extern __shared__ char smc[];
    float* sbias = (float*)smc;
    bf16* sa = (bf16*)(smc + 1024);
    const int n0 = blockIdx.x * 128, m0 = blockIdx.y * 128;
    if (threadIdx.x < 128) sbias[threadIdx.x] = bias[n0 + threadIdx.x];

    float acc[4][4][4];
#pragma unroll
    for (int a = 0; a < 4; a++)
#pragma unroll
        for (int b = 0; b < 4; b++)
#pragma unroll
            for (int cc = 0; cc < 4; cc++) acc[a][b][cc] = 0.f;

    gemm_ml(acc, g_atthi, g_attlo, g_wprojhi, g_wprojlo, m0, n0, sa);

    const int wid = threadIdx.x >> 5, lane = threadIdx.x & 31;
    const int wm = wid & 1, wn = wid >> 1;
    const int r = lane >> 2, c4 = lane & 3;
#pragma unroll
    for (int mf = 0; mf < 4; mf++)
#pragma unroll
        for (int nf = 0; nf < 4; nf++) {
            const int m = wm * 64 + mf * 16 + r;
            const int n = wn * 32 + nf * 8 + c4 * 2;
            const float b0 = sbias[n], b1 = sbias[n + 1];
            *(float2*)&out[(size_t)(m0 + m) * C_ + n0 + n] =
                make_float2(acc[mf][nf][0] + b0, acc[mf][nf][1] + b1);
            *(float2*)&out[(size_t)(m0 + m + 8) * C_ + n0 + n] =
                make_float2(acc[mf][nf][2] + b0, acc[mf][nf][3] + b1);
        }
}

// ---------------------------------------------------------------------------
extern "C" void kernel_launch(void* const* d_in, const int* in_sizes, int n_in,
                              void* d_out, int out_size) {
    const float*         x      = (const float*)d_in[0];
    const unsigned char* mask   = (const unsigned char*)d_in[1];
    const float*         w_qkv  = (const float*)d_in[2];
    const float*         w_proj = (const float*)d_in[3];
    const float*         b_proj = (const float*)d_in[4];
    const float*         qg     = (const float*)d_in[5];
    const float*         qb     = (const float*)d_in[6];
    const float*         kg     = (const float*)d_in[7];
    const float*         kb     = (const float*)d_in[8];
    float* out = (float*)d_out;

    conv_kernel<<<4096, 256>>>(x, 0, (B_ * N_ * C_) / 4);
    conv_kernel<<<3072, 256>>>(w_qkv, 1, (3 * C_ * C_) / 4);
    conv_kernel<<<1024, 256>>>(w_proj, 2, (C_ * C_) / 4);

    cudaFuncSetAttribute(qkv_mma_kernel, cudaFuncAttributeMaxDynamicSharedMemorySize, SMEM_GEMM);
    qkv_mma_kernel<<<dim3(24, 32), 256, SMEM_GEMM>>>(qg, qb, kg, kb);

    vt_kernel<<<dim3(N_ / 64, B_ * H_), 256>>>();

    cudaFuncSetAttribute(flash_mma_kernel, cudaFuncAttributeMaxDynamicSharedMemorySize, SMEM_FLASH);
    flash_mma_kernel<<<dim3(N_ / 128, H_, B_), 256, SMEM_FLASH>>>(mask);

    cudaFuncSetAttribute(proj_mma_kernel, cudaFuncAttributeMaxDynamicSharedMemorySize, SMEM_GEMM);
    proj_mma_kernel<<<dim3(8, 32), 256, SMEM_GEMM>>>(b_proj, out);
}

// round 7
// speedup vs baseline: 1.4002x; 1.4002x over previous
#include <cuda_runtime.h>
#include <cuda_bf16.h>
#include <cfloat>
#include <cstdint>

#define B_ 2
#define N_ 2048
#define C_ 1024
#define H_ 16
#define D_ 64

typedef __nv_bfloat16 bf16;

// ---------------------------------------------------------------------------
// Scratch (allocation-free rule: __device__ globals)
// ---------------------------------------------------------------------------
__device__ float g_v[B_ * H_ * N_ * D_];
__device__ bf16 g_qhi[B_ * H_ * N_ * D_], g_qlo[B_ * H_ * N_ * D_];
__device__ bf16 g_khi[B_ * H_ * N_ * D_], g_klo[B_ * H_ * N_ * D_];
__device__ bf16 g_vthi[B_ * H_ * D_ * N_], g_vtlo[B_ * H_ * D_ * N_];
__device__ bf16 g_xhi[B_ * N_ * C_], g_xlo[B_ * N_ * C_];
__device__ bf16 g_wqkvhi[3 * C_ * C_], g_wqkvlo[3 * C_ * C_];
__device__ bf16 g_wprojhi[C_ * C_], g_wprojlo[C_ * C_];
__device__ bf16 g_atthi[B_ * N_ * C_], g_attlo[B_ * N_ * C_];

// ---------------------------------------------------------------------------
// Family-agnostic PTX helpers
// ---------------------------------------------------------------------------
__device__ __forceinline__ uint32_t smem_u32(const void* p) {
    uint32_t a;
    asm("{ .reg .u64 t; cvta.to.shared.u64 t, %1; cvt.u32.u64 %0, t; }" : "=r"(a) : "l"(p));
    return a;
}
#define CP16(saddr, gptr) \
    asm volatile("cp.async.cg.shared.global [%0], [%1], 16;" ::"r"(saddr), "l"(gptr) : "memory")
#define CP_COMMIT() asm volatile("cp.async.commit_group;" ::: "memory")
#define CP_WAIT0()  asm volatile("cp.async.wait_group 0;" ::: "memory")

__device__ __forceinline__ void mma_bf16(float c[4], uint32_t a0, uint32_t a1, uint32_t a2,
                                         uint32_t a3, uint32_t b0, uint32_t b1) {
    asm volatile(
        "mma.sync.aligned.m16n8k16.row.col.f32.bf16.bf16.f32 "
        "{%0,%1,%2,%3},{%4,%5,%6,%7},{%8,%9},{%0,%1,%2,%3};"
        : "+f"(c[0]), "+f"(c[1]), "+f"(c[2]), "+f"(c[3])
        : "r"(a0), "r"(a1), "r"(a2), "r"(a3), "r"(b0), "r"(b1));
}

__device__ __forceinline__ uint32_t pack_bf16(bf16 lo, bf16 hi) {
    __nv_bfloat162 t; t.x = lo; t.y = hi;
    return *(uint32_t*)&t;
}
__device__ __forceinline__ void split2(float x, float y, uint32_t& hp, uint32_t& lp) {
    bf16 hx = __float2bfloat16_rn(x), hy = __float2bfloat16_rn(y);
    float lx = x - __bfloat162float(hx), ly = y - __bfloat162float(hy);
    hp = pack_bf16(hx, hy);
    lp = pack_bf16(__float2bfloat16_rn(lx), __float2bfloat16_rn(ly));
}

// ---------------------------------------------------------------------------
// 128x128x1024 split-bf16 (3-pass) mma.sync mainloop — pass-major MMA order
// (consecutive MMAs hit different accumulators; dep distance 16).
// ---------------------------------------------------------------------------
#define PITCH 40
#define CH (128 * PITCH)
#define CHB (CH * 2)
#define SMEM_GEMM (1024 + 8 * CHB)

__device__ __forceinline__ void gemm_ml(float acc[4][4][4],
                                        const bf16* __restrict__ Ahi,
                                        const bf16* __restrict__ Alo,
                                        const bf16* __restrict__ Bhi,
                                        const bf16* __restrict__ Blo,
                                        int m0, int n0, bf16* sa) {
    const int tid = threadIdx.x;
    const int wid = tid >> 5, lane = tid & 31;
    const int wm = wid & 1, wn = wid >> 1;
    const int r = lane >> 2, c4 = lane & 3;
    const int grow = tid >> 1, gcol = (tid & 1) * 16;

    const uint32_t sab = smem_u32(sa);
    const uint32_t so = (uint32_t)(grow * PITCH + gcol) * 2;

    const bf16* pAh = Ahi + (size_t)(m0 + grow) * C_ + gcol;
    const bf16* pAl = Alo + (size_t)(m0 + grow) * C_ + gcol;
    const bf16* pBh = Bhi + (size_t)(n0 + grow) * C_ + gcol;
    const bf16* pBl = Blo + (size_t)(n0 + grow) * C_ + gcol;

    {
        CP16(sab + 0 * CHB + so,      pAh);
        CP16(sab + 0 * CHB + so + 16, pAh + 8);
        CP16(sab + 2 * CHB + so,      pAl);
        CP16(sab + 2 * CHB + so + 16, pAl + 8);
        CP16(sab + 4 * CHB + so,      pBh);
        CP16(sab + 4 * CHB + so + 16, pBh + 8);
        CP16(sab + 6 * CHB + so,      pBl);
        CP16(sab + 6 * CHB + so + 16, pBl + 8);
        CP_COMMIT();
        CP_WAIT0();
    }
    __syncthreads();

    for (int c = 0; c < 32; c++) {
        if (c < 31) {
            const int k0 = (c + 1) * 32;
            const uint32_t nb = (uint32_t)((c + 1) & 1) * CHB;
            CP16(sab + 0 * CHB + nb + so,      pAh + k0);
            CP16(sab + 0 * CHB + nb + so + 16, pAh + k0 + 8);
            CP16(sab + 2 * CHB + nb + so,      pAl + k0);
            CP16(sab + 2 * CHB + nb + so + 16, pAl + k0 + 8);
            CP16(sab + 4 * CHB + nb + so,      pBh + k0);
            CP16(sab + 4 * CHB + nb + so + 16, pBh + k0 + 8);
            CP16(sab + 6 * CHB + nb + so,      pBl + k0);
            CP16(sab + 6 * CHB + nb + so + 16, pBl + k0 + 8);
            CP_COMMIT();
        }
        const int bo = (c & 1) * CH;
        const bf16* ah = sa + bo;
        const bf16* al = sa + 2 * CH + bo;
        const bf16* bh = sa + 4 * CH + bo;
        const bf16* bl = sa + 6 * CH + bo;
#pragma unroll
        for (int kf = 0; kf < 2; kf++) {
            const int kb = kf * 16 + c4 * 2;
            uint32_t afh[4][4], afl[4][4];
#pragma unroll
            for (int mf = 0; mf < 4; mf++) {
                const int row = wm * 64 + mf * 16 + r;
                afh[mf][0] = *(const uint32_t*)(ah + row * PITCH + kb);
                afh[mf][1] = *(const uint32_t*)(ah + (row + 8) * PITCH + kb);
                afh[mf][2] = *(const uint32_t*)(ah + row * PITCH + kb + 8);
                afh[mf][3] = *(const uint32_t*)(ah + (row + 8) * PITCH + kb + 8);
                afl[mf][0] = *(const uint32_t*)(al + row * PITCH + kb);
                afl[mf][1] = *(const uint32_t*)(al + (row + 8) * PITCH + kb);
                afl[mf][2] = *(const uint32_t*)(al + row * PITCH + kb + 8);
                afl[mf][3] = *(const uint32_t*)(al + (row + 8) * PITCH + kb + 8);
            }
            uint32_t bfh[4][2], bfl[4][2];
#pragma unroll
            for (int nf = 0; nf < 4; nf++) {
                const int nn = wn * 32 + nf * 8 + r;
                bfh[nf][0] = *(const uint32_t*)(bh + nn * PITCH + kb);
                bfh[nf][1] = *(const uint32_t*)(bh + nn * PITCH + kb + 8);
                bfl[nf][0] = *(const uint32_t*)(bl + nn * PITCH + kb);
                bfl[nf][1] = *(const uint32_t*)(bl + nn * PITCH + kb + 8);
            }
            // pass-major: 16 independent accumulators per pass
#pragma unroll
            for (int mf = 0; mf < 4; mf++)
#pragma unroll
                for (int nf = 0; nf < 4; nf++)
                    mma_bf16(acc[mf][nf], afh[mf][0], afh[mf][1], afh[mf][2], afh[mf][3],
                             bfh[nf][0], bfh[nf][1]);
#pragma unroll
            for (int mf = 0; mf < 4; mf++)
#pragma unroll
                for (int nf = 0; nf < 4; nf++)
                    mma_bf16(acc[mf][nf], afh[mf][0], afh[mf][1], afh[mf][2], afh[mf][3],
                             bfl[nf][0], bfl[nf][1]);
#pragma unroll
            for (int mf = 0; mf < 4; mf++)
#pragma unroll
                for (int nf = 0; nf < 4; nf++)
                    mma_bf16(acc[mf][nf], afl[mf][0], afl[mf][1], afl[mf][2], afl[mf][3],
                             bfh[nf][0], bfh[nf][1]);
        }
        if (c < 31) CP_WAIT0();
        __syncthreads();
    }
}

// ---------------------------------------------------------------------------
// fp32 -> (hi, lo) bf16 split
// ---------------------------------------------------------------------------
__global__ __launch_bounds__(256) void conv_kernel(const float* __restrict__ src,
                                                   int sel, int n4) {
    bf16* hi = (sel == 0) ? g_xhi : (sel == 1) ? g_wqkvhi : g_wprojhi;
    bf16* lo = (sel == 0) ? g_xlo : (sel == 1) ? g_wqkvlo : g_wprojlo;
    int i = blockIdx.x * 256 + threadIdx.x;
    if (i >= n4) return;
    float4 v = ((const float4*)src)[i];
    uint32_t hp[2], lp[2];
    split2(v.x, v.y, hp[0], lp[0]);
    split2(v.z, v.w, hp[1], lp[1]);
    *(uint32_t*)(hi + 4 * (size_t)i)     = hp[0];
    *(uint32_t*)(hi + 4 * (size_t)i + 2) = hp[1];
    *(uint32_t*)(lo + 4 * (size_t)i)     = lp[0];
    *(uint32_t*)(lo + 4 * (size_t)i + 2) = lp[1];
}

// ---------------------------------------------------------------------------
// QKV GEMM + fused per-head LayerNorm; Q,K out as bf16 hi/lo; V out fp32.
// ---------------------------------------------------------------------------
#define DPITCH 132

__global__ __launch_bounds__(256) void qkv_mma_kernel(const float* __restrict__ qg,
                                                      const float* __restrict__ qb,
                                                      const float* __restrict__ kg,
                                                      const float* __restrict__ kb) {
    extern __shared__ char smc[];
    float* sgam = (float*)smc;
    float* sbet = (float*)(smc + 256);
    bf16* sa = (bf16*)(smc + 1024);

    const int n0 = blockIdx.x * 128, m0 = blockIdx.y * 128;
    const int s = n0 >> 10;
    if (threadIdx.x < 64 && s < 2) {
        const float* gg = (s == 0) ? qg : kg;
        const float* bb = (s == 0) ? qb : kb;
        sgam[threadIdx.x] = gg[threadIdx.x];
        sbet[threadIdx.x] = bb[threadIdx.x];
    }

    float acc[4][4][4];
#pragma unroll
    for (int a = 0; a < 4; a++)
#pragma unroll
        for (int b = 0; b < 4; b++)
#pragma unroll
            for (int cc = 0; cc < 4; cc++) acc[a][b][cc] = 0.f;

    gemm_ml(acc, g_xhi, g_xlo, g_wqkvhi, g_wqkvlo, m0, n0, sa);

    float* Dst = (float*)(smc + 1024);
    const int wid = threadIdx.x >> 5, lane = threadIdx.x & 31;
    const int wm = wid & 1, wn = wid >> 1;
    const int r = lane >> 2, c4 = lane & 3;
#pragma unroll
    for (int mf = 0; mf < 4; mf++)
#pragma unroll
        for (int nf = 0; nf < 4; nf++) {
            const int m = wm * 64 + mf * 16 + r;
            const int n = wn * 32 + nf * 8 + c4 * 2;
            *(float2*)&Dst[m * DPITCH + n]       = make_float2(acc[mf][nf][0], acc[mf][nf][1]);
            *(float2*)&Dst[(m + 8) * DPITCH + n] = make_float2(acc[mf][nf][2], acc[mf][nf][3]);
        }
    __syncthreads();

    const int m = threadIdx.x >> 1, hc = threadIdx.x & 1;
    const float* rowp = Dst + m * DPITCH + hc * 64;
    float f[64];
#pragma unroll
    for (int i = 0; i < 64; i++) f[i] = rowp[i];
    const int bidx = m0 >> 11, nq = (m0 & 2047) + m;
    const int h = ((n0 & 1023) >> 6) + hc;
    const size_t base = (((size_t)(bidx * H_ + h)) * N_ + nq) * D_;
    if (s < 2) {
        float sum = 0.f;
#pragma unroll
        for (int i = 0; i < 64; i++) sum += f[i];
        float mu = sum * (1.0f / 64.0f);
        float vs = 0.f;
#pragma unroll
        for (int i = 0; i < 64; i++) { float d = f[i] - mu; vs += d * d; }
        float rs = rsqrtf(vs * (1.0f / 64.0f) + 1e-5f);
#pragma unroll
        for (int i = 0; i < 64; i++) f[i] = (f[i] - mu) * rs * sgam[i] + sbet[i];
        bf16* dh = (s == 0) ? g_qhi : g_khi;
        bf16* dl = (s == 0) ? g_qlo : g_klo;
#pragma unroll
        for (int i = 0; i < 64; i += 2) {
            uint32_t hp, lp;
            split2(f[i], f[i + 1], hp, lp);
            *(uint32_t*)(dh + base + i) = hp;
            *(uint32_t*)(dl + base + i) = lp;
        }
    } else {
#pragma unroll
        for (int i = 0; i < 64; i += 4)
            *(float4*)&g_v[base + i] = make_float4(f[i], f[i + 1], f[i + 2], f[i + 3]);
    }
}

// ---------------------------------------------------------------------------
// V transpose + split:  g_v[b,h,key,d] -> g_vthi/lo[b,h,d,key]
// ---------------------------------------------------------------------------
__global__ __launch_bounds__(256) void vt_kernel() {
    __shared__ float tile[64][65];
    const int kt = blockIdx.x, bh = blockIdx.y;
    const int tid = threadIdx.x;
    const float* src = g_v + (size_t)bh * N_ * D_ + (size_t)(kt * 64) * D_;
#pragma unroll
    for (int j = 0; j < 4; j++) {
        int id = tid + j * 256;
        int row = id >> 4, c4i = (id & 15) * 4;
        float4 v = *(const float4*)(src + row * D_ + c4i);
        tile[row][c4i] = v.x; tile[row][c4i + 1] = v.y;
        tile[row][c4i + 2] = v.z; tile[row][c4i + 3] = v.w;
    }
    __syncthreads();
    const int d = tid >> 2, kg = (tid & 3) * 16;
    bf16* dh = g_vthi + (size_t)bh * D_ * N_ + (size_t)d * N_ + kt * 64 + kg;
    bf16* dl = g_vtlo + (size_t)bh * D_ * N_ + (size_t)d * N_ + kt * 64 + kg;
#pragma unroll
    for (int i = 0; i < 16; i += 2) {
        uint32_t hp, lp;
        split2(tile[kg + i][d], tile[kg + i + 1][d], hp, lp);
        *(uint32_t*)(dh + i) = hp;
        *(uint32_t*)(dl + i) = lp;
    }
}

// ---------------------------------------------------------------------------
// Flash attention on mma.sync (split-bf16, pass-major MMA order).
// CTA: 128 q-rows, 8 warps (16 rows each), Bc = 64 keys/iter.
// ---------------------------------------------------------------------------
#define FP 72
#define KTILE (64 * FP)
#define SMEM_FLASH (8 * KTILE * 2)

__global__ __launch_bounds__(256) void flash_mma_kernel(const unsigned char* __restrict__ mask) {
    extern __shared__ char smc[];
    bf16* sh = (bf16*)smc;
    const uint32_t shb = smem_u32(sh);

    const int qt = blockIdx.x, h = blockIdx.y, b = blockIdx.z;
    const int tid = threadIdx.x, wid = tid >> 5, lane = tid & 31;
    const int r = lane >> 2, c4 = lane & 3;
    const int wrow = wid * 16;
    const size_t qkoff = ((size_t)(b * H_ + h)) * N_ * D_;
    const size_t vtoff = ((size_t)(b * H_ + h)) * D_ * N_;

    // ---- stage Q tile and read fragments ----
    {
        const bf16* qh = g_qhi + qkoff + (size_t)(qt * 128) * D_;
        const bf16* ql = g_qlo + qkoff + (size_t)(qt * 128) * D_;
#pragma unroll
        for (int j = 0; j < 4; j++) {
            int id = tid + j * 256;
            int row = id >> 3, c8 = (id & 7) * 8;
            CP16(shb + (row * FP + c8) * 2, qh + row * D_ + c8);
            CP16(shb + (2 * KTILE + row * FP + c8) * 2, ql + row * D_ + c8);
        }
        CP_COMMIT(); CP_WAIT0();
    }
    __syncthreads();

    uint32_t aQh[4][4], aQl[4][4];
#pragma unroll
    for (int kc = 0; kc < 4; kc++) {
        const int ba = (wrow + r) * FP + kc * 16 + c4 * 2;
        aQh[kc][0] = *(const uint32_t*)(sh + ba);
        aQh[kc][1] = *(const uint32_t*)(sh + ba + 8 * FP);
        aQh[kc][2] = *(const uint32_t*)(sh + ba + 8);
        aQh[kc][3] = *(const uint32_t*)(sh + ba + 8 * FP + 8);
        aQl[kc][0] = *(const uint32_t*)(sh + 2 * KTILE + ba);
        aQl[kc][1] = *(const uint32_t*)(sh + 2 * KTILE + ba + 8 * FP);
        aQl[kc][2] = *(const uint32_t*)(sh + 2 * KTILE + ba + 8);
        aQl[kc][3] = *(const uint32_t*)(sh + 2 * KTILE + ba + 8 * FP + 8);
    }
    __syncthreads();

    float of[8][4];
#pragma unroll
    for (int nb = 0; nb < 8; nb++)
#pragma unroll
        for (int k = 0; k < 4; k++) of[nb][k] = 0.f;
    float mI0 = -FLT_MAX, mI1 = -FLT_MAX, l0 = 0.f, l1 = 0.f;

    auto issue_tile = [&](int kt2, int buf) {
        const uint32_t bo = (uint32_t)buf * 4 * KTILE * 2;
        const bf16* kh = g_khi + qkoff + (size_t)(kt2 * 64) * D_;
        const bf16* kl = g_klo + qkoff + (size_t)(kt2 * 64) * D_;
        const bf16* vh = g_vthi + vtoff + kt2 * 64;
        const bf16* vl = g_vtlo + vtoff + kt2 * 64;
#pragma unroll
        for (int j = 0; j < 2; j++) {
            int id = tid + j * 256;
            int row = id >> 3, c8 = (id & 7) * 8;
            uint32_t sd = bo + (row * FP + c8) * 2;
            CP16(shb + sd, kh + row * D_ + c8);
            CP16(shb + sd + KTILE * 2, kl + row * D_ + c8);
            CP16(shb + sd + 2 * KTILE * 2, vh + (size_t)row * N_ + c8);
            CP16(shb + sd + 3 * KTILE * 2, vl + (size_t)row * N_ + c8);
        }
        CP_COMMIT();
    };

    issue_tile(0, 0);
    CP_WAIT0();
    __syncthreads();

    const unsigned char* mb0 = mask + ((size_t)b * N_ + qt * 128 + wrow + r) * N_;
    const float scale = 0.125f;

    for (int kt2 = 0; kt2 < N_ / 64; kt2++) {
        if (kt2 < N_ / 64 - 1) issue_tile(kt2 + 1, (kt2 + 1) & 1);

        const bf16* sKh = sh + ((kt2 & 1) * 4 + 0) * KTILE;
        const bf16* sKl = sh + ((kt2 & 1) * 4 + 1) * KTILE;
        const bf16* sVh = sh + ((kt2 & 1) * 4 + 2) * KTILE;
        const bf16* sVl = sh + ((kt2 & 1) * 4 + 3) * KTILE;

        // ---- S = Q K^T (3-pass, pass-major per group of 4 accumulators) ----
        float sf[8][4];
#pragma unroll
        for (int nb = 0; nb < 8; nb++)
            sf[nb][0] = sf[nb][1] = sf[nb][2] = sf[nb][3] = 0.f;

#pragma unroll
        for (int kc = 0; kc < 4; kc++) {
#pragma unroll
            for (int g = 0; g < 2; g++) {
                uint32_t kh0[4], kh1[4], kl0[4], kl1[4];
#pragma unroll
                for (int j = 0; j < 4; j++) {
                    const int nb = g * 4 + j;
                    const int kb = (nb * 8 + r) * FP + kc * 16 + c4 * 2;
                    kh0[j] = *(const uint32_t*)(sKh + kb);
                    kh1[j] = *(const uint32_t*)(sKh + kb + 8);
                    kl0[j] = *(const uint32_t*)(sKl + kb);
                    kl1[j] = *(const uint32_t*)(sKl + kb + 8);
                }
#pragma unroll
                for (int j = 0; j < 4; j++)
                    mma_bf16(sf[g * 4 + j], aQh[kc][0], aQh[kc][1], aQh[kc][2], aQh[kc][3],
                             kh0[j], kh1[j]);
#pragma unroll
                for (int j = 0; j < 4; j++)
                    mma_bf16(sf[g * 4 + j], aQh[kc][0], aQh[kc][1], aQh[kc][2], aQh[kc][3],
                             kl0[j], kl1[j]);
#pragma unroll
                for (int j = 0; j < 4; j++)
                    mma_bf16(sf[g * 4 + j], aQl[kc][0], aQl[kc][1], aQl[kc][2], aQl[kc][3],
                             kh0[j], kh1[j]);
            }
        }

        // ---- scale + mask ----
        const unsigned char* mr0 = mb0 + kt2 * 64 + c4 * 2;
#pragma unroll
        for (int nb = 0; nb < 8; nb++) {
            uchar2 k0 = *(const uchar2*)(mr0 + nb * 8);
            uchar2 k8 = *(const uchar2*)(mr0 + 8 * N_ + nb * 8);
            sf[nb][0] = k0.x ? -FLT_MAX : sf[nb][0] * scale;
            sf[nb][1] = k0.y ? -FLT_MAX : sf[nb][1] * scale;
            sf[nb][2] = k8.x ? -FLT_MAX : sf[nb][2] * scale;
            sf[nb][3] = k8.y ? -FLT_MAX : sf[nb][3] * scale;
        }

        // ---- online softmax ----
        float mx0 = -FLT_MAX, mx1 = -FLT_MAX;
#pragma unroll
        for (int nb = 0; nb < 8; nb++) {
            mx0 = fmaxf(mx0, fmaxf(sf[nb][0], sf[nb][1]));
            mx1 = fmaxf(mx1, fmaxf(sf[nb][2], sf[nb][3]));
        }
        mx0 = fmaxf(mx0, __shfl_xor_sync(0xffffffffu, mx0, 1));
        mx0 = fmaxf(mx0, __shfl_xor_sync(0xffffffffu, mx0, 2));
        mx1 = fmaxf(mx1, __shfl_xor_sync(0xffffffffu, mx1, 1));
        mx1 = fmaxf(mx1, __shfl_xor_sync(0xffffffffu, mx1, 2));
        const float mn0 = fmaxf(mI0, mx0), mn1 = fmaxf(mI1, mx1);
        const float cor0 = __expf(mI0 - mn0), cor1 = __expf(mI1 - mn1);
        mI0 = mn0; mI1 = mn1;
        float rs0 = 0.f, rs1 = 0.f;
#pragma unroll
        for (int nb = 0; nb < 8; nb++) {
            sf[nb][0] = __expf(sf[nb][0] - mn0);
            sf[nb][1] = __expf(sf[nb][1] - mn0);
            sf[nb][2] = __expf(sf[nb][2] - mn1);
            sf[nb][3] = __expf(sf[nb][3] - mn1);
            rs0 += sf[nb][0] + sf[nb][1];
            rs1 += sf[nb][2] + sf[nb][3];
        }
        rs0 += __shfl_xor_sync(0xffffffffu, rs0, 1);
        rs0 += __shfl_xor_sync(0xffffffffu, rs0, 2);
        rs1 += __shfl_xor_sync(0xffffffffu, rs1, 1);
        rs1 += __shfl_xor_sync(0xffffffffu, rs1, 2);
        l0 = l0 * cor0 + rs0;
        l1 = l1 * cor1 + rs1;
#pragma unroll
        for (int nb = 0; nb < 8; nb++) {
            of[nb][0] *= cor0; of[nb][1] *= cor0;
            of[nb][2] *= cor1; of[nb][3] *= cor1;
        }

        // ---- O += P V (3-pass, pass-major per group of 4 accumulators) ----
#pragma unroll
        for (int kc = 0; kc < 4; kc++) {
            uint32_t ah[4], al[4];
            split2(sf[2 * kc][0], sf[2 * kc][1], ah[0], al[0]);
            split2(sf[2 * kc][2], sf[2 * kc][3], ah[1], al[1]);
            split2(sf[2 * kc + 1][0], sf[2 * kc + 1][1], ah[2], al[2]);
            split2(sf[2 * kc + 1][2], sf[2 * kc + 1][3], ah[3], al[3]);
#pragma unroll
            for (int g = 0; g < 2; g++) {
                uint32_t vh0[4], vh1[4], vl0[4], vl1[4];
#pragma unroll
                for (int j = 0; j < 4; j++) {
                    const int nb = g * 4 + j;
                    const int vb = (nb * 8 + r) * FP + kc * 16 + c4 * 2;
                    vh0[j] = *(const uint32_t*)(sVh + vb);
                    vh1[j] = *(const uint32_t*)(sVh + vb + 8);
                    vl0[j] = *(const uint32_t*)(sVl + vb);
                    vl1[j] = *(const uint32_t*)(sVl + vb + 8);
                }
#pragma unroll
                for (int j = 0; j < 4; j++)
                    mma_bf16(of[g * 4 + j], ah[0], ah[1], ah[2], ah[3], vh0[j], vh1[j]);
#pragma unroll
                for (int j = 0; j < 4; j++)
                    mma_bf16(of[g * 4 + j], ah[0], ah[1], ah[2], ah[3], vl0[j], vl1[j]);
#pragma unroll
                for (int j = 0; j < 4; j++)
                    mma_bf16(of[g * 4 + j], al[0], al[1], al[2], al[3], vh0[j], vh1[j]);
            }
        }

        if (kt2 < N_ / 64 - 1) CP_WAIT0();
        __syncthreads();
    }

    // ---- epilogue ----
    const float inv0 = 1.0f / l0, inv1 = 1.0f / l1;
    const int row0 = qt * 128 + wrow + r;
    const size_t ob0 = ((size_t)b * N_ + row0) * C_ + h * 64 + c4 * 2;
    const size_t ob1 = ob0 + 8 * (size_t)C_;
#pragma unroll
    for (int nb = 0; nb < 8; nb++) {
        uint32_t hp, lp;
        split2(of[nb][0] * inv0, of[nb][1] * inv0, hp, lp);
        *(uint32_t*)(g_atthi + ob0 + nb * 8) = hp;
        *(uint32_t*)(g_attlo + ob0 + nb * 8) = lp;
        split2(of[nb][2] * inv1, of[nb][3] * inv1, hp, lp);
        *(uint32_t*)(g_atthi + ob1 + nb * 8) = hp;
        *(uint32_t*)(g_attlo + ob1 + nb * 8) = lp;
    }
}

// ---------------------------------------------------------------------------
// Projection GEMM + bias
// ---------------------------------------------------------------------------
__global__ __launch_bounds__(256) void proj_mma_kernel(const float* __restrict__ bias,
                                                       float* __restrict__ out) {
    extern __shared__ char smc[];
    float* sbias = (float*)smc;
    bf16* sa = (bf16*)(smc + 1024);
    const int n0 = blockIdx.x * 128, m0 = blockIdx.y * 128;
    if (threadIdx.x < 128) sbias[threadIdx.x] = bias[n0 + threadIdx.x];

    float acc[4][4][4];
#pragma unroll
    for (int a = 0; a < 4; a++)
#pragma unroll
        for (int b = 0; b < 4; b++)
#pragma unroll
            for (int cc = 0; cc < 4; cc++) acc[a][b][cc] = 0.f;

    gemm_ml(acc, g_atthi, g_attlo, g_wprojhi, g_wprojlo, m0, n0, sa);

    const int wid = threadIdx.x >> 5, lane = threadIdx.x & 31;
    const int wm = wid & 1, wn = wid >> 1;
    const int r = lane >> 2, c4 = lane & 3;
#pragma unroll
    for (int mf = 0; mf < 4; mf++)
#pragma unroll
        for (int nf = 0; nf < 4; nf++) {
            const int m = wm * 64 + mf * 16 + r;
            const int n = wn * 32 + nf * 8 + c4 * 2;
            const float b0 = sbias[n], b1 = sbias[n + 1];
            *(float2*)&out[(size_t)(m0 + m) * C_ + n0 + n] =
                make_float2(acc[mf][nf][0] + b0, acc[mf][nf][1] + b1);
            *(float2*)&out[(size_t)(m0 + m + 8) * C_ + n0 + n] =
                make_float2(acc[mf][nf][2] + b0, acc[mf][nf][3] + b1);
        }
}

// ---------------------------------------------------------------------------
extern "C" void kernel_launch(void* const* d_in, const int* in_sizes, int n_in,
                              void* d_out, int out_size) {
    const float*         x      = (const float*)d_in[0];
    const unsigned char* mask   = (const unsigned char*)d_in[1];
    const float*         w_qkv  = (const float*)d_in[2];
    const float*         w_proj = (const float*)d_in[3];
    const float*         b_proj = (const float*)d_in[4];
    const float*         qg     = (const float*)d_in[5];
    const float*         qb     = (const float*)d_in[6];
    const float*         kg     = (const float*)d_in[7];
    const float*         kb     = (const float*)d_in[8];
    float* out = (float*)d_out;

    conv_kernel<<<4096, 256>>>(x, 0, (B_ * N_ * C_) / 4);
    conv_kernel<<<3072, 256>>>(w_qkv, 1, (3 * C_ * C_) / 4);
    conv_kernel<<<1024, 256>>>(w_proj, 2, (C_ * C_) / 4);

    cudaFuncSetAttribute(qkv_mma_kernel, cudaFuncAttributeMaxDynamicSharedMemorySize, SMEM_GEMM);
    qkv_mma_kernel<<<dim3(24, 32), 256, SMEM_GEMM>>>(qg, qb, kg, kb);

    vt_kernel<<<dim3(N_ / 64, B_ * H_), 256>>>();

    cudaFuncSetAttribute(flash_mma_kernel, cudaFuncAttributeMaxDynamicSharedMemorySize, SMEM_FLASH);
    flash_mma_kernel<<<dim3(N_ / 128, H_, B_), 256, SMEM_FLASH>>>(mask);

    cudaFuncSetAttribute(proj_mma_kernel, cudaFuncAttributeMaxDynamicSharedMemorySize, SMEM_GEMM);
    proj_mma_kernel<<<dim3(8, 32), 256, SMEM_GEMM>>>(b_proj, out);
}

// round 9
// speedup vs baseline: 1.4195x; 1.0138x over previous
#include <cuda_runtime.h>
#include <cuda_bf16.h>
#include <cfloat>
#include <cstdint>

#define B_ 2
#define N_ 2048
#define C_ 1024
#define H_ 16
#define D_ 64

typedef __nv_bfloat16 bf16;

// ---------------------------------------------------------------------------
// Scratch (allocation-free rule: __device__ globals)
// ---------------------------------------------------------------------------
__device__ float g_v[B_ * H_ * N_ * D_];
__device__ bf16 g_qhi[B_ * H_ * N_ * D_], g_qlo[B_ * H_ * N_ * D_];
__device__ bf16 g_khi[B_ * H_ * N_ * D_], g_klo[B_ * H_ * N_ * D_];
__device__ bf16 g_vthi[B_ * H_ * D_ * N_], g_vtlo[B_ * H_ * D_ * N_];
__device__ bf16 g_xhi[B_ * N_ * C_], g_xlo[B_ * N_ * C_];
__device__ bf16 g_wqkvhi[3 * C_ * C_], g_wqkvlo[3 * C_ * C_];
__device__ bf16 g_wprojhi[C_ * C_], g_wprojlo[C_ * C_];
__device__ bf16 g_atthi[B_ * N_ * C_], g_attlo[B_ * N_ * C_];

// ---------------------------------------------------------------------------
// Family-agnostic PTX helpers
// ---------------------------------------------------------------------------
__device__ __forceinline__ uint32_t smem_u32(const void* p) {
    uint32_t a;
    asm("{ .reg .u64 t; cvta.to.shared.u64 t, %1; cvt.u32.u64 %0, t; }" : "=r"(a) : "l"(p));
    return a;
}
#define CP16(saddr, gptr) \
    asm volatile("cp.async.cg.shared.global [%0], [%1], 16;" ::"r"(saddr), "l"(gptr) : "memory")
#define CP_COMMIT() asm volatile("cp.async.commit_group;" ::: "memory")
#define CP_WAIT0()  asm volatile("cp.async.wait_group 0;" ::: "memory")

__device__ __forceinline__ void mma_bf16(float c[4], uint32_t a0, uint32_t a1, uint32_t a2,
                                         uint32_t a3, uint32_t b0, uint32_t b1) {
    asm volatile(
        "mma.sync.aligned.m16n8k16.row.col.f32.bf16.bf16.f32 "
        "{%0,%1,%2,%3},{%4,%5,%6,%7},{%8,%9},{%0,%1,%2,%3};"
        : "+f"(c[0]), "+f"(c[1]), "+f"(c[2]), "+f"(c[3])
        : "r"(a0), "r"(a1), "r"(a2), "r"(a3), "r"(b0), "r"(b1));
}

__device__ __forceinline__ uint32_t pack_bf16(bf16 lo, bf16 hi) {
    __nv_bfloat162 t; t.x = lo; t.y = hi;
    return *(uint32_t*)&t;
}
__device__ __forceinline__ void split2(float x, float y, uint32_t& hp, uint32_t& lp) {
    bf16 hx = __float2bfloat16_rn(x), hy = __float2bfloat16_rn(y);
    float lx = x - __bfloat162float(hx), ly = y - __bfloat162float(hy);
    hp = pack_bf16(hx, hy);
    lp = pack_bf16(__float2bfloat16_rn(lx), __float2bfloat16_rn(ly));
}

// ---------------------------------------------------------------------------
// 128x128x1024 split-bf16 (3-pass) mainloop.
// 128 threads = 4 warps (2 x 2), warp tile 64x64 → 0.67 frag-loads per MMA.
// ---------------------------------------------------------------------------
#define PITCH 40
#define CH (128 * PITCH)
#define CHB (CH * 2)
#define SMEM_GEMM (1024 + 8 * CHB)

__device__ __forceinline__ void gemm_ml(float acc[4][8][4],
                                        const bf16* __restrict__ Ahi,
                                        const bf16* __restrict__ Alo,
                                        const bf16* __restrict__ Bhi,
                                        const bf16* __restrict__ Blo,
                                        int m0, int n0, bf16* sa) {
    const int tid = threadIdx.x;            // 0..127
    const int wid = tid >> 5, lane = tid & 31;
    const int wm = wid & 1, wn = wid >> 1;  // 2x2 warps, 64x64 each
    const int r = lane >> 2, c4 = lane & 3;
    const int row = tid;                    // loader row 0..127

    const uint32_t sab = smem_u32(sa);
    const uint32_t so = (uint32_t)(row * PITCH) * 2;

    const bf16* pAh = Ahi + (size_t)(m0 + row) * C_;
    const bf16* pAl = Alo + (size_t)(m0 + row) * C_;
    const bf16* pBh = Bhi + (size_t)(n0 + row) * C_;
    const bf16* pBl = Blo + (size_t)(n0 + row) * C_;

    // prefetch chunk 0 into buffer 0 (each thread: one row x 32 halves x 4 arrays)
    {
#pragma unroll
        for (int q = 0; q < 4; q++) {
            CP16(sab + 0 * CHB + so + q * 16, pAh + q * 8);
            CP16(sab + 2 * CHB + so + q * 16, pAl + q * 8);
            CP16(sab + 4 * CHB + so + q * 16, pBh + q * 8);
            CP16(sab + 6 * CHB + so + q * 16, pBl + q * 8);
        }
        CP_COMMIT();
        CP_WAIT0();
    }
    __syncthreads();

    for (int c = 0; c < 32; c++) {
        if (c < 31) {
            const int k0 = (c + 1) * 32;
            const uint32_t nb = (uint32_t)((c + 1) & 1) * CHB;
#pragma unroll
            for (int q = 0; q < 4; q++) {
                CP16(sab + 0 * CHB + nb + so + q * 16, pAh + k0 + q * 8);
                CP16(sab + 2 * CHB + nb + so + q * 16, pAl + k0 + q * 8);
                CP16(sab + 4 * CHB + nb + so + q * 16, pBh + k0 + q * 8);
                CP16(sab + 6 * CHB + nb + so + q * 16, pBl + k0 + q * 8);
            }
            CP_COMMIT();
        }
        const int bo = (c & 1) * CH;
        const bf16* ah = sa + bo;
        const bf16* al = sa + 2 * CH + bo;
        const bf16* bh = sa + 4 * CH + bo;
        const bf16* bl = sa + 6 * CH + bo;
#pragma unroll
        for (int kf = 0; kf < 2; kf++) {
            const int kb = kf * 16 + c4 * 2;
            uint32_t afh[4][4], afl[4][4];
#pragma unroll
            for (int mf = 0; mf < 4; mf++) {
                const int rr = wm * 64 + mf * 16 + r;
                afh[mf][0] = *(const uint32_t*)(ah + rr * PITCH + kb);
                afh[mf][1] = *(const uint32_t*)(ah + (rr + 8) * PITCH + kb);
                afh[mf][2] = *(const uint32_t*)(ah + rr * PITCH + kb + 8);
                afh[mf][3] = *(const uint32_t*)(ah + (rr + 8) * PITCH + kb + 8);
                afl[mf][0] = *(const uint32_t*)(al + rr * PITCH + kb);
                afl[mf][1] = *(const uint32_t*)(al + (rr + 8) * PITCH + kb);
                afl[mf][2] = *(const uint32_t*)(al + rr * PITCH + kb + 8);
                afl[mf][3] = *(const uint32_t*)(al + (rr + 8) * PITCH + kb + 8);
            }
            uint32_t bfh[8][2], bfl[8][2];
#pragma unroll
            for (int nf = 0; nf < 8; nf++) {
                const int nn = wn * 64 + nf * 8 + r;
                bfh[nf][0] = *(const uint32_t*)(bh + nn * PITCH + kb);
                bfh[nf][1] = *(const uint32_t*)(bh + nn * PITCH + kb + 8);
                bfl[nf][0] = *(const uint32_t*)(bl + nn * PITCH + kb);
                bfl[nf][1] = *(const uint32_t*)(bl + nn * PITCH + kb + 8);
            }
#pragma unroll
            for (int mf = 0; mf < 4; mf++)
#pragma unroll
                for (int nf = 0; nf < 8; nf++) {
                    mma_bf16(acc[mf][nf], afh[mf][0], afh[mf][1], afh[mf][2], afh[mf][3],
                             bfh[nf][0], bfh[nf][1]);
                    mma_bf16(acc[mf][nf], afh[mf][0], afh[mf][1], afh[mf][2], afh[mf][3],
                             bfl[nf][0], bfl[nf][1]);
                    mma_bf16(acc[mf][nf], afl[mf][0], afl[mf][1], afl[mf][2], afl[mf][3],
                             bfh[nf][0], bfh[nf][1]);
                }
        }
        if (c < 31) CP_WAIT0();
        __syncthreads();
    }
}

// ---------------------------------------------------------------------------
// fp32 -> (hi, lo) bf16 split
// ---------------------------------------------------------------------------
__global__ __launch_bounds__(256) void conv_kernel(const float* __restrict__ src,
                                                   int sel, int n4) {
    bf16* hi = (sel == 0) ? g_xhi : (sel == 1) ? g_wqkvhi : g_wprojhi;
    bf16* lo = (sel == 0) ? g_xlo : (sel == 1) ? g_wqkvlo : g_wprojlo;
    int i = blockIdx.x * 256 + threadIdx.x;
    if (i >= n4) return;
    float4 v = ((const float4*)src)[i];
    uint32_t hp[2], lp[2];
    split2(v.x, v.y, hp[0], lp[0]);
    split2(v.z, v.w, hp[1], lp[1]);
    *(uint32_t*)(hi + 4 * (size_t)i)     = hp[0];
    *(uint32_t*)(hi + 4 * (size_t)i + 2) = hp[1];
    *(uint32_t*)(lo + 4 * (size_t)i)     = lp[0];
    *(uint32_t*)(lo + 4 * (size_t)i + 2) = lp[1];
}

// ---------------------------------------------------------------------------
// QKV GEMM + fused per-head LayerNorm; Q,K out as bf16 hi/lo; V out fp32.
// grid (24, 32), 128 threads.
// ---------------------------------------------------------------------------
#define DPITCH 132

__global__ __launch_bounds__(128) void qkv_mma_kernel(const float* __restrict__ qg,
                                                      const float* __restrict__ qb,
                                                      const float* __restrict__ kg,
                                                      const float* __restrict__ kb) {
    extern __shared__ char smc[];
    float* sgam = (float*)smc;
    float* sbet = (float*)(smc + 256);
    bf16* sa = (bf16*)(smc + 1024);

    const int n0 = blockIdx.x * 128, m0 = blockIdx.y * 128;
    const int s = n0 >> 10;
    if (threadIdx.x < 64 && s < 2) {
        const float* gg = (s == 0) ? qg : kg;
        const float* bb = (s == 0) ? qb : kb;
        sgam[threadIdx.x] = gg[threadIdx.x];
        sbet[threadIdx.x] = bb[threadIdx.x];
    }

    float acc[4][8][4];
#pragma unroll
    for (int a = 0; a < 4; a++)
#pragma unroll
        for (int b = 0; b < 8; b++)
#pragma unroll
            for (int cc = 0; cc < 4; cc++) acc[a][b][cc] = 0.f;

    gemm_ml(acc, g_xhi, g_xlo, g_wqkvhi, g_wqkvlo, m0, n0, sa);

    float* Dst = (float*)(smc + 1024);
    const int wid = threadIdx.x >> 5, lane = threadIdx.x & 31;
    const int wm = wid & 1, wn = wid >> 1;
    const int r = lane >> 2, c4 = lane & 3;
#pragma unroll
    for (int mf = 0; mf < 4; mf++)
#pragma unroll
        for (int nf = 0; nf < 8; nf++) {
            const int m = wm * 64 + mf * 16 + r;
            const int n = wn * 64 + nf * 8 + c4 * 2;
            *(float2*)&Dst[m * DPITCH + n]       = make_float2(acc[mf][nf][0], acc[mf][nf][1]);
            *(float2*)&Dst[(m + 8) * DPITCH + n] = make_float2(acc[mf][nf][2], acc[mf][nf][3]);
        }
    __syncthreads();

    const int m = threadIdx.x;           // one row per thread, both heads
    const int bidx = m0 >> 11, nq = (m0 & 2047) + m;
#pragma unroll
    for (int hc = 0; hc < 2; hc++) {
        const float* rowp = Dst + m * DPITCH + hc * 64;
        float f[64];
#pragma unroll
        for (int i = 0; i < 64; i++) f[i] = rowp[i];
        const int h = ((n0 & 1023) >> 6) + hc;
        const size_t base = (((size_t)(bidx * H_ + h)) * N_ + nq) * D_;
        if (s < 2) {
            float sum = 0.f;
#pragma unroll
            for (int i = 0; i < 64; i++) sum += f[i];
            float mu = sum * (1.0f / 64.0f);
            float vs = 0.f;
#pragma unroll
            for (int i = 0; i < 64; i++) { float d = f[i] - mu; vs += d * d; }
            float rs = rsqrtf(vs * (1.0f / 64.0f) + 1e-5f);
#pragma unroll
            for (int i = 0; i < 64; i++) f[i] = (f[i] - mu) * rs * sgam[i] + sbet[i];
            bf16* dh = (s == 0) ? g_qhi : g_khi;
            bf16* dl = (s == 0) ? g_qlo : g_klo;
#pragma unroll
            for (int i = 0; i < 64; i += 2) {
                uint32_t hp, lp;
                split2(f[i], f[i + 1], hp, lp);
                *(uint32_t*)(dh + base + i) = hp;
                *(uint32_t*)(dl + base + i) = lp;
            }
        } else {
#pragma unroll
            for (int i = 0; i < 64; i += 4)
                *(float4*)&g_v[base + i] = make_float4(f[i], f[i + 1], f[i + 2], f[i + 3]);
        }
    }
}

// ---------------------------------------------------------------------------
// V transpose + split:  g_v[b,h,key,d] -> g_vthi/lo[b,h,d,key]
// ---------------------------------------------------------------------------
__global__ __launch_bounds__(256) void vt_kernel() {
    __shared__ float tile[64][65];
    const int kt = blockIdx.x, bh = blockIdx.y;
    const int tid = threadIdx.x;
    const float* src = g_v + (size_t)bh * N_ * D_ + (size_t)(kt * 64) * D_;
#pragma unroll
    for (int j = 0; j < 4; j++) {
        int id = tid + j * 256;
        int row = id >> 4, c4i = (id & 15) * 4;
        float4 v = *(const float4*)(src + row * D_ + c4i);
        tile[row][c4i] = v.x; tile[row][c4i + 1] = v.y;
        tile[row][c4i + 2] = v.z; tile[row][c4i + 3] = v.w;
    }
    __syncthreads();
    const int d = tid >> 2, kg = (tid & 3) * 16;
    bf16* dh = g_vthi + (size_t)bh * D_ * N_ + (size_t)d * N_ + kt * 64 + kg;
    bf16* dl = g_vtlo + (size_t)bh * D_ * N_ + (size_t)d * N_ + kt * 64 + kg;
#pragma unroll
    for (int i = 0; i < 16; i += 2) {
        uint32_t hp, lp;
        split2(tile[kg + i][d], tile[kg + i + 1][d], hp, lp);
        *(uint32_t*)(dh + i) = hp;
        *(uint32_t*)(dl + i) = lp;
    }
}

// ---------------------------------------------------------------------------
// Flash attention on mma.sync (split-bf16), 128 threads = 4 warps.
// Warp = 32 q-rows (2 m-frags) -> K/V fragments amortized over 2x MMAs.
// SMEM (halves): [0, QREG) resident Q-lo; [QREG, QREG+8*KT) K/V double buffer.
// Q-hi staged transiently in buf1 (overwritten after frags are in registers).
// ---------------------------------------------------------------------------
#define FP 72
#define KT (64 * FP)        // 4608 halves per K/V array
#define QREG (128 * FP)     // 9216 halves
#define SMEM_FLASH ((QREG + 8 * KT) * 2)   // 92160 bytes

__global__ __launch_bounds__(128) void flash_mma_kernel(const unsigned char* __restrict__ mask) {
    extern __shared__ char smc[];
    bf16* sh = (bf16*)smc;
    const uint32_t shb = smem_u32(sh);

    const int qt = blockIdx.x, h = blockIdx.y, b = blockIdx.z;
    const int tid = threadIdx.x, wid = tid >> 5, lane = tid & 31;
    const int r = lane >> 2, c4 = lane & 3;
    const int wrow = wid * 32;                       // 32 rows per warp
    const size_t qkoff = ((size_t)(b * H_ + h)) * N_ * D_;
    const size_t vtoff = ((size_t)(b * H_ + h)) * D_ * N_;

    const uint32_t qhi_base = (uint32_t)(QREG + 4 * KT);   // halves (buf1 area)

    // ---- stage Q: hi -> buf1 area (transient), lo -> resident region ----
    {
        const bf16* qh = g_qhi + qkoff + (size_t)(qt * 128) * D_;
        const bf16* ql = g_qlo + qkoff + (size_t)(qt * 128) * D_;
#pragma unroll
        for (int j = 0; j < 8; j++) {
            int id = tid + j * 128;
            int row = id >> 3, c8 = (id & 7) * 8;
            CP16(shb + (qhi_base + row * FP + c8) * 2, qh + row * D_ + c8);
            CP16(shb + (row * FP + c8) * 2,            ql + row * D_ + c8);
        }
        CP_COMMIT();
    }

    // ---- first K/V tile into buf0 (no overlap with Q-hi staging in buf1) ----
    auto issue_tile = [&](int kt2, int buf) {
        const uint32_t bo = (uint32_t)(QREG + buf * 4 * KT) * 2;
        const bf16* kh = g_khi + qkoff + (size_t)(kt2 * 64) * D_;
        const bf16* kl = g_klo + qkoff + (size_t)(kt2 * 64) * D_;
        const bf16* vh = g_vthi + vtoff + kt2 * 64;
        const bf16* vl = g_vtlo + vtoff + kt2 * 64;
#pragma unroll
        for (int j = 0; j < 4; j++) {
            int id = tid + j * 128;
            int row = id >> 3, c8 = (id & 7) * 8;
            uint32_t sd = bo + (row * FP + c8) * 2;
            CP16(shb + sd,              kh + row * D_ + c8);
            CP16(shb + sd + KT * 2,     kl + row * D_ + c8);
            CP16(shb + sd + 2 * KT * 2, vh + (size_t)row * N_ + c8);
            CP16(shb + sd + 3 * KT * 2, vl + (size_t)row * N_ + c8);
        }
        CP_COMMIT();
    };
    issue_tile(0, 0);
    CP_WAIT0();
    __syncthreads();

    // ---- Q-hi fragments to registers (2 m-frags x 4 k-chunks) ----
    uint32_t aQh[2][4][4];
#pragma unroll
    for (int mf = 0; mf < 2; mf++)
#pragma unroll
        for (int kc = 0; kc < 4; kc++) {
            const int ba = qhi_base + (wrow + mf * 16 + r) * FP + kc * 16 + c4 * 2;
            aQh[mf][kc][0] = *(const uint32_t*)(sh + ba);
            aQh[mf][kc][1] = *(const uint32_t*)(sh + ba + 8 * FP);
            aQh[mf][kc][2] = *(const uint32_t*)(sh + ba + 8);
            aQh[mf][kc][3] = *(const uint32_t*)(sh + ba + 8 * FP + 8);
        }
    __syncthreads();   // all warps done reading Q-hi before buf1 prefetch

    float of[2][8][4];
#pragma unroll
    for (int mf = 0; mf < 2; mf++)
#pragma unroll
        for (int nb = 0; nb < 8; nb++)
#pragma unroll
            for (int k = 0; k < 4; k++) of[mf][nb][k] = 0.f;
    float mI[2][2], lI[2][2];
#pragma unroll
    for (int mf = 0; mf < 2; mf++) {
        mI[mf][0] = mI[mf][1] = -FLT_MAX;
        lI[mf][0] = lI[mf][1] = 0.f;
    }

    const unsigned char* mb[2];
    mb[0] = mask + ((size_t)b * N_ + qt * 128 + wrow + r) * N_;
    mb[1] = mb[0] + 16 * (size_t)N_;
    const float scale = 0.125f;

    for (int kt2 = 0; kt2 < N_ / 64; kt2++) {
        if (kt2 < N_ / 64 - 1) issue_tile(kt2 + 1, (kt2 + 1) & 1);

        const bf16* sKh = sh + QREG + ((kt2 & 1) * 4 + 0) * KT;
        const bf16* sKl = sh + QREG + ((kt2 & 1) * 4 + 1) * KT;
        const bf16* sVh = sh + QREG + ((kt2 & 1) * 4 + 2) * KT;
        const bf16* sVl = sh + QREG + ((kt2 & 1) * 4 + 3) * KT;

        // ---- S = Q K^T (3-pass); K frags shared by both m-frags ----
        float sf[2][8][4];
#pragma unroll
        for (int mf = 0; mf < 2; mf++)
#pragma unroll
            for (int nb = 0; nb < 8; nb++)
                sf[mf][nb][0] = sf[mf][nb][1] = sf[mf][nb][2] = sf[mf][nb][3] = 0.f;

#pragma unroll
        for (int kc = 0; kc < 4; kc++) {
            // Q-lo frags for this kc (from resident SMEM)
            uint32_t ql[2][4];
#pragma unroll
            for (int mf = 0; mf < 2; mf++) {
                const int ba = (wrow + mf * 16 + r) * FP + kc * 16 + c4 * 2;
                ql[mf][0] = *(const uint32_t*)(sh + ba);
                ql[mf][1] = *(const uint32_t*)(sh + ba + 8 * FP);
                ql[mf][2] = *(const uint32_t*)(sh + ba + 8);
                ql[mf][3] = *(const uint32_t*)(sh + ba + 8 * FP + 8);
            }
#pragma unroll
            for (int g = 0; g < 2; g++) {
                uint32_t kh0[4], kh1[4], kl0[4], kl1[4];
#pragma unroll
                for (int j = 0; j < 4; j++) {
                    const int kb = ((g * 4 + j) * 8 + r) * FP + kc * 16 + c4 * 2;
                    kh0[j] = *(const uint32_t*)(sKh + kb);
                    kh1[j] = *(const uint32_t*)(sKh + kb + 8);
                    kl0[j] = *(const uint32_t*)(sKl + kb);
                    kl1[j] = *(const uint32_t*)(sKl + kb + 8);
                }
#pragma unroll
                for (int mf = 0; mf < 2; mf++) {
#pragma unroll
                    for (int j = 0; j < 4; j++)
                        mma_bf16(sf[mf][g * 4 + j], aQh[mf][kc][0], aQh[mf][kc][1],
                                 aQh[mf][kc][2], aQh[mf][kc][3], kh0[j], kh1[j]);
#pragma unroll
                    for (int j = 0; j < 4; j++)
                        mma_bf16(sf[mf][g * 4 + j], aQh[mf][kc][0], aQh[mf][kc][1],
                                 aQh[mf][kc][2], aQh[mf][kc][3], kl0[j], kl1[j]);
#pragma unroll
                    for (int j = 0; j < 4; j++)
                        mma_bf16(sf[mf][g * 4 + j], ql[mf][0], ql[mf][1],
                                 ql[mf][2], ql[mf][3], kh0[j], kh1[j]);
                }
            }
        }

        // ---- scale + mask + online softmax (per m-frag) ----
#pragma unroll
        for (int mf = 0; mf < 2; mf++) {
            const unsigned char* mr0 = mb[mf] + kt2 * 64 + c4 * 2;
#pragma unroll
            for (int nb = 0; nb < 8; nb++) {
                uchar2 k0 = *(const uchar2*)(mr0 + nb * 8);
                uchar2 k8 = *(const uchar2*)(mr0 + 8 * N_ + nb * 8);
                sf[mf][nb][0] = k0.x ? -FLT_MAX : sf[mf][nb][0] * scale;
                sf[mf][nb][1] = k0.y ? -FLT_MAX : sf[mf][nb][1] * scale;
                sf[mf][nb][2] = k8.x ? -FLT_MAX : sf[mf][nb][2] * scale;
                sf[mf][nb][3] = k8.y ? -FLT_MAX : sf[mf][nb][3] * scale;
            }
            float mx0 = -FLT_MAX, mx1 = -FLT_MAX;
#pragma unroll
            for (int nb = 0; nb < 8; nb++) {
                mx0 = fmaxf(mx0, fmaxf(sf[mf][nb][0], sf[mf][nb][1]));
                mx1 = fmaxf(mx1, fmaxf(sf[mf][nb][2], sf[mf][nb][3]));
            }
            mx0 = fmaxf(mx0, __shfl_xor_sync(0xffffffffu, mx0, 1));
            mx0 = fmaxf(mx0, __shfl_xor_sync(0xffffffffu, mx0, 2));
            mx1 = fmaxf(mx1, __shfl_xor_sync(0xffffffffu, mx1, 1));
            mx1 = fmaxf(mx1, __shfl_xor_sync(0xffffffffu, mx1, 2));
            const float mn0 = fmaxf(mI[mf][0], mx0), mn1 = fmaxf(mI[mf][1], mx1);
            const float cor0 = __expf(mI[mf][0] - mn0), cor1 = __expf(mI[mf][1] - mn1);
            mI[mf][0] = mn0; mI[mf][1] = mn1;
            float rs0 = 0.f, rs1 = 0.f;
#pragma unroll
            for (int nb = 0; nb < 8; nb++) {
                sf[mf][nb][0] = __expf(sf[mf][nb][0] - mn0);
                sf[mf][nb][1] = __expf(sf[mf][nb][1] - mn0);
                sf[mf][nb][2] = __expf(sf[mf][nb][2] - mn1);
                sf[mf][nb][3] = __expf(sf[mf][nb][3] - mn1);
                rs0 += sf[mf][nb][0] + sf[mf][nb][1];
                rs1 += sf[mf][nb][2] + sf[mf][nb][3];
            }
            rs0 += __shfl_xor_sync(0xffffffffu, rs0, 1);
            rs0 += __shfl_xor_sync(0xffffffffu, rs0, 2);
            rs1 += __shfl_xor_sync(0xffffffffu, rs1, 1);
            rs1 += __shfl_xor_sync(0xffffffffu, rs1, 2);
            lI[mf][0] = lI[mf][0] * cor0 + rs0;
            lI[mf][1] = lI[mf][1] * cor1 + rs1;
#pragma unroll
            for (int nb = 0; nb < 8; nb++) {
                of[mf][nb][0] *= cor0; of[mf][nb][1] *= cor0;
                of[mf][nb][2] *= cor1; of[mf][nb][3] *= cor1;
            }
        }

        // ---- O += P V (3-pass); V frags shared by both m-frags ----
#pragma unroll
        for (int kc = 0; kc < 4; kc++) {
            uint32_t ph[2][4], pl[2][4];
#pragma unroll
            for (int mf = 0; mf < 2; mf++) {
                split2(sf[mf][2 * kc][0], sf[mf][2 * kc][1], ph[mf][0], pl[mf][0]);
                split2(sf[mf][2 * kc][2], sf[mf][2 * kc][3], ph[mf][1], pl[mf][1]);
                split2(sf[mf][2 * kc + 1][0], sf[mf][2 * kc + 1][1], ph[mf][2], pl[mf][2]);
                split2(sf[mf][2 * kc + 1][2], sf[mf][2 * kc + 1][3], ph[mf][3], pl[mf][3]);
            }
#pragma unroll
            for (int g = 0; g < 2; g++) {
                uint32_t vh0[4], vh1[4], vl0[4], vl1[4];
#pragma unroll
                for (int j = 0; j < 4; j++) {
                    const int vb = ((g * 4 + j) * 8 + r) * FP + kc * 16 + c4 * 2;
                    vh0[j] = *(const uint32_t*)(sVh + vb);
                    vh1[j] = *(const uint32_t*)(sVh + vb + 8);
                    vl0[j] = *(const uint32_t*)(sVl + vb);
                    vl1[j] = *(const uint32_t*)(sVl + vb + 8);
                }
#pragma unroll
                for (int mf = 0; mf < 2; mf++) {
#pragma unroll
                    for (int j = 0; j < 4; j++)
                        mma_bf16(of[mf][g * 4 + j], ph[mf][0], ph[mf][1], ph[mf][2], ph[mf][3],
                                 vh0[j], vh1[j]);
#pragma unroll
                    for (int j = 0; j < 4; j++)
                        mma_bf16(of[mf][g * 4 + j], ph[mf][0], ph[mf][1], ph[mf][2], ph[mf][3],
                                 vl0[j], vl1[j]);
#pragma unroll
                    for (int j = 0; j < 4; j++)
                        mma_bf16(of[mf][g * 4 + j], pl[mf][0], pl[mf][1], pl[mf][2], pl[mf][3],
                                 vh0[j], vh1[j]);
                }
            }
        }

        if (kt2 < N_ / 64 - 1) CP_WAIT0();
        __syncthreads();
    }

    // ---- epilogue: normalize, write split bf16 att [B,N,C] ----
#pragma unroll
    for (int mf = 0; mf < 2; mf++) {
        const float inv0 = 1.0f / lI[mf][0], inv1 = 1.0f / lI[mf][1];
        const int row0 = qt * 128 + wrow + mf * 16 + r;
        const size_t ob0 = ((size_t)b * N_ + row0) * C_ + h * 64 + c4 * 2;
        const size_t ob1 = ob0 + 8 * (size_t)C_;
#pragma unroll
        for (int nb = 0; nb < 8; nb++) {
            uint32_t hp, lp;
            split2(of[mf][nb][0] * inv0, of[mf][nb][1] * inv0, hp, lp);
            *(uint32_t*)(g_atthi + ob0 + nb * 8) = hp;
            *(uint32_t*)(g_attlo + ob0 + nb * 8) = lp;
            split2(of[mf][nb][2] * inv1, of[mf][nb][3] * inv1, hp, lp);
            *(uint32_t*)(g_atthi + ob1 + nb * 8) = hp;
            *(uint32_t*)(g_attlo + ob1 + nb * 8) = lp;
        }
    }
}

// ---------------------------------------------------------------------------
// Projection GEMM + bias. grid (8, 32), 128 threads.
// ---------------------------------------------------------------------------
__global__ __launch_bounds__(128) void proj_mma_kernel(const float* __restrict__ bias,
                                                       float* __restrict__ out) {
    extern __shared__ char smc[];
    float* sbias = (float*)smc;
    bf16* sa = (bf16*)(smc + 1024);
    const int n0 = blockIdx.x * 128, m0 = blockIdx.y * 128;
    if (threadIdx.x < 128) sbias[threadIdx.x] = bias[n0 + threadIdx.x];

    float acc[4][8][4];
#pragma unroll
    for (int a = 0; a < 4; a++)
#pragma unroll
        for (int b = 0; b < 8; b++)
#pragma unroll
            for (int cc = 0; cc < 4; cc++) acc[a][b][cc] = 0.f;

    gemm_ml(acc, g_atthi, g_attlo, g_wprojhi, g_wprojlo, m0, n0, sa);

    const int wid = threadIdx.x >> 5, lane = threadIdx.x & 31;
    const int wm = wid & 1, wn = wid >> 1;
    const int r = lane >> 2, c4 = lane & 3;
#pragma unroll
    for (int mf = 0; mf < 4; mf++)
#pragma unroll
        for (int nf = 0; nf < 8; nf++) {
            const int m = wm * 64 + mf * 16 + r;
            const int n = wn * 64 + nf * 8 + c4 * 2;
            const float b0 = sbias[n], b1 = sbias[n + 1];
            *(float2*)&out[(size_t)(m0 + m) * C_ + n0 + n] =
                make_float2(acc[mf][nf][0] + b0, acc[mf][nf][1] + b1);
            *(float2*)&out[(size_t)(m0 + m + 8) * C_ + n0 + n] =
                make_float2(acc[mf][nf][2] + b0, acc[mf][nf][3] + b1);
        }
}

// ---------------------------------------------------------------------------
extern "C" void kernel_launch(void* const* d_in, const int* in_sizes, int n_in,
                              void* d_out, int out_size) {
    const float*         x      = (const float*)d_in[0];
    const unsigned char* mask   = (const unsigned char*)d_in[1];
    const float*         w_qkv  = (const float*)d_in[2];
    const float*         w_proj = (const float*)d_in[3];
    const float*         b_proj = (const float*)d_in[4];
    const float*         qg     = (const float*)d_in[5];
    const float*         qb     = (const float*)d_in[6];
    const float*         kg     = (const float*)d_in[7];
    const float*         kb     = (const float*)d_in[8];
    float* out = (float*)d_out;

    conv_kernel<<<4096, 256>>>(x, 0, (B_ * N_ * C_) / 4);
    conv_kernel<<<3072, 256>>>(w_qkv, 1, (3 * C_ * C_) / 4);
    conv_kernel<<<1024, 256>>>(w_proj, 2, (C_ * C_) / 4);

    cudaFuncSetAttribute(qkv_mma_kernel, cudaFuncAttributeMaxDynamicSharedMemorySize, SMEM_GEMM);
    qkv_mma_kernel<<<dim3(24, 32), 128, SMEM_GEMM>>>(qg, qb, kg, kb);

    vt_kernel<<<dim3(N_ / 64, B_ * H_), 256>>>();

    cudaFuncSetAttribute(flash_mma_kernel, cudaFuncAttributeMaxDynamicSharedMemorySize, SMEM_FLASH);
    flash_mma_kernel<<<dim3(N_ / 128, H_, B_), 128, SMEM_FLASH>>>(mask);

    cudaFuncSetAttribute(proj_mma_kernel, cudaFuncAttributeMaxDynamicSharedMemorySize, SMEM_GEMM);
    proj_mma_kernel<<<dim3(8, 32), 128, SMEM_GEMM>>>(b_proj, out);
}

// round 11
// speedup vs baseline: 2.1537x; 1.5173x over previous
#include <cuda_runtime.h>
#include <cuda_fp16.h>
#include <cfloat>
#include <cstdint>

#define B_ 2
#define N_ 2048
#define C_ 1024
#define H_ 16
#define D_ 64

typedef __half h16;

// ---------------------------------------------------------------------------
// Scratch (allocation-free rule: __device__ globals)
// ---------------------------------------------------------------------------
__device__ float g_v[B_ * H_ * N_ * D_];
__device__ h16 g_qhi[B_ * H_ * N_ * D_], g_qlo[B_ * H_ * N_ * D_];
__device__ h16 g_khi[B_ * H_ * N_ * D_];
__device__ h16 g_vthi[B_ * H_ * D_ * N_];
__device__ h16 g_xhi[B_ * N_ * C_], g_xlo[B_ * N_ * C_];
__device__ h16 g_wqkvhi[3 * C_ * C_];
__device__ h16 g_wprojhi[C_ * C_];
__device__ h16 g_atthi[B_ * N_ * C_], g_attlo[B_ * N_ * C_];

// ---------------------------------------------------------------------------
// Family-agnostic PTX helpers
// ---------------------------------------------------------------------------
__device__ __forceinline__ uint32_t smem_u32(const void* p) {
    uint32_t a;
    asm("{ .reg .u64 t; cvta.to.shared.u64 t, %1; cvt.u32.u64 %0, t; }" : "=r"(a) : "l"(p));
    return a;
}
#define CP16(saddr, gptr) \
    asm volatile("cp.async.cg.shared.global [%0], [%1], 16;" ::"r"(saddr), "l"(gptr) : "memory")
#define CP_COMMIT() asm volatile("cp.async.commit_group;" ::: "memory")
#define CP_WAIT0()  asm volatile("cp.async.wait_group 0;" ::: "memory")

__device__ __forceinline__ void mma_f16(float c[4], uint32_t a0, uint32_t a1, uint32_t a2,
                                        uint32_t a3, uint32_t b0, uint32_t b1) {
    asm volatile(
        "mma.sync.aligned.m16n8k16.row.col.f32.f16.f16.f32 "
        "{%0,%1,%2,%3},{%4,%5,%6,%7},{%8,%9},{%0,%1,%2,%3};"
        : "+f"(c[0]), "+f"(c[1]), "+f"(c[2]), "+f"(c[3])
        : "r"(a0), "r"(a1), "r"(a2), "r"(a3), "r"(b0), "r"(b1));
}

__device__ __forceinline__ uint32_t pack_h2(h16 a, h16 b) {
    __half2 t; t.x = a; t.y = b;
    return *(uint32_t*)&t;
}
__device__ __forceinline__ uint32_t pack_hi2(float x, float y) {
    return pack_h2(__float2half_rn(x), __float2half_rn(y));
}
// split (x,y) -> packed fp16 hi-pair and lo-pair (hi+lo captures ~22 bits)
__device__ __forceinline__ void split2h(float x, float y, uint32_t& hp, uint32_t& lp) {
    h16 hx = __float2half_rn(x), hy = __float2half_rn(y);
    hp = pack_h2(hx, hy);
    lp = pack_h2(__float2half_rn(x - __half2float(hx)),
                 __float2half_rn(y - __half2float(hy)));
}

// ---------------------------------------------------------------------------
// 128x128x1024 fp16 2-pass mainloop: (Ahi + Alo) x Bhi.
// 256 threads = 8 warps (2 x 4), warp tile 64x32, K-chunk 32, double buffered.
// ---------------------------------------------------------------------------
#define PITCH 40
#define CH (128 * PITCH)
#define CHB (CH * 2)
// smem must also cover the 128 x 132 fp32 staging region used by qkv epilogue
#define DPITCH 132
#define SMEM_GEMM (1024 + 128 * DPITCH * 4)   // 68608 >= 1024 + 6*CHB (62464)

__device__ __forceinline__ void gemm_ml(float acc[4][4][4],
                                        const h16* __restrict__ Ahi,
                                        const h16* __restrict__ Alo,
                                        const h16* __restrict__ Bhi,
                                        int m0, int n0, h16* sa) {
    const int tid = threadIdx.x;
    const int wid = tid >> 5, lane = tid & 31;
    const int wm = wid & 1, wn = wid >> 1;
    const int r = lane >> 2, c4 = lane & 3;
    const int grow = tid >> 1, gcol = (tid & 1) * 16;

    const uint32_t sab = smem_u32(sa);
    const uint32_t so = (uint32_t)(grow * PITCH + gcol) * 2;

    const h16* pAh = Ahi + (size_t)(m0 + grow) * C_ + gcol;
    const h16* pAl = Alo + (size_t)(m0 + grow) * C_ + gcol;
    const h16* pBh = Bhi + (size_t)(n0 + grow) * C_ + gcol;

    {
        CP16(sab + 0 * CHB + so,      pAh);
        CP16(sab + 0 * CHB + so + 16, pAh + 8);
        CP16(sab + 2 * CHB + so,      pAl);
        CP16(sab + 2 * CHB + so + 16, pAl + 8);
        CP16(sab + 4 * CHB + so,      pBh);
        CP16(sab + 4 * CHB + so + 16, pBh + 8);
        CP_COMMIT();
        CP_WAIT0();
    }
    __syncthreads();

    for (int c = 0; c < 32; c++) {
        if (c < 31) {
            const int k0 = (c + 1) * 32;
            const uint32_t nb = (uint32_t)((c + 1) & 1) * CHB;
            CP16(sab + 0 * CHB + nb + so,      pAh + k0);
            CP16(sab + 0 * CHB + nb + so + 16, pAh + k0 + 8);
            CP16(sab + 2 * CHB + nb + so,      pAl + k0);
            CP16(sab + 2 * CHB + nb + so + 16, pAl + k0 + 8);
            CP16(sab + 4 * CHB + nb + so,      pBh + k0);
            CP16(sab + 4 * CHB + nb + so + 16, pBh + k0 + 8);
            CP_COMMIT();
        }
        const int bo = (c & 1) * CH;
        const h16* ah = sa + bo;
        const h16* al = sa + 2 * CH + bo;
        const h16* bh = sa + 4 * CH + bo;
#pragma unroll
        for (int kf = 0; kf < 2; kf++) {
            const int kb = kf * 16 + c4 * 2;
            uint32_t afh[4][4], afl[4][4];
#pragma unroll
            for (int mf = 0; mf < 4; mf++) {
                const int row = wm * 64 + mf * 16 + r;
                afh[mf][0] = *(const uint32_t*)(ah + row * PITCH + kb);
                afh[mf][1] = *(const uint32_t*)(ah + (row + 8) * PITCH + kb);
                afh[mf][2] = *(const uint32_t*)(ah + row * PITCH + kb + 8);
                afh[mf][3] = *(const uint32_t*)(ah + (row + 8) * PITCH + kb + 8);
                afl[mf][0] = *(const uint32_t*)(al + row * PITCH + kb);
                afl[mf][1] = *(const uint32_t*)(al + (row + 8) * PITCH + kb);
                afl[mf][2] = *(const uint32_t*)(al + row * PITCH + kb + 8);
                afl[mf][3] = *(const uint32_t*)(al + (row + 8) * PITCH + kb + 8);
            }
            uint32_t bfh[4][2];
#pragma unroll
            for (int nf = 0; nf < 4; nf++) {
                const int nn = wn * 32 + nf * 8 + r;
                bfh[nf][0] = *(const uint32_t*)(bh + nn * PITCH + kb);
                bfh[nf][1] = *(const uint32_t*)(bh + nn * PITCH + kb + 8);
            }
#pragma unroll
            for (int mf = 0; mf < 4; mf++)
#pragma unroll
                for (int nf = 0; nf < 4; nf++)
                    mma_f16(acc[mf][nf], afh[mf][0], afh[mf][1], afh[mf][2], afh[mf][3],
                            bfh[nf][0], bfh[nf][1]);
#pragma unroll
            for (int mf = 0; mf < 4; mf++)
#pragma unroll
                for (int nf = 0; nf < 4; nf++)
                    mma_f16(acc[mf][nf], afl[mf][0], afl[mf][1], afl[mf][2], afl[mf][3],
                            bfh[nf][0], bfh[nf][1]);
        }
        if (c < 31) CP_WAIT0();
        __syncthreads();
    }
}

// ---------------------------------------------------------------------------
// fp32 -> fp16 split. sel 0 = x (hi+lo); sel 1 = w_qkv (hi); sel 2 = w_proj (hi).
// ---------------------------------------------------------------------------
__global__ __launch_bounds__(256) void conv_kernel(const float* __restrict__ src,
                                                   int sel, int n4) {
    int i = blockIdx.x * 256 + threadIdx.x;
    if (i >= n4) return;
    float4 v = ((const float4*)src)[i];
    if (sel == 0) {
        uint32_t hp[2], lp[2];
        split2h(v.x, v.y, hp[0], lp[0]);
        split2h(v.z, v.w, hp[1], lp[1]);
        *(uint32_t*)(g_xhi + 4 * (size_t)i)     = hp[0];
        *(uint32_t*)(g_xhi + 4 * (size_t)i + 2) = hp[1];
        *(uint32_t*)(g_xlo + 4 * (size_t)i)     = lp[0];
        *(uint32_t*)(g_xlo + 4 * (size_t)i + 2) = lp[1];
    } else {
        h16* hi = (sel == 1) ? g_wqkvhi : g_wprojhi;
        *(uint32_t*)(hi + 4 * (size_t)i)     = pack_hi2(v.x, v.y);
        *(uint32_t*)(hi + 4 * (size_t)i + 2) = pack_hi2(v.z, v.w);
    }
}

// ---------------------------------------------------------------------------
// QKV GEMM + fused per-head LayerNorm.
// Q out: fp16 hi+lo; K out: fp16 hi; V out: fp32. grid (24, 32), 256 threads.
// ---------------------------------------------------------------------------
__global__ __launch_bounds__(256) void qkv_mma_kernel(const float* __restrict__ qg,
                                                      const float* __restrict__ qb,
                                                      const float* __restrict__ kg,
                                                      const float* __restrict__ kb) {
    extern __shared__ char smc[];
    float* sgam = (float*)smc;
    float* sbet = (float*)(smc + 256);
    h16* sa = (h16*)(smc + 1024);

    const int n0 = blockIdx.x * 128, m0 = blockIdx.y * 128;
    const int s = n0 >> 10;
    if (threadIdx.x < 64 && s < 2) {
        const float* gg = (s == 0) ? qg : kg;
        const float* bb = (s == 0) ? qb : kb;
        sgam[threadIdx.x] = gg[threadIdx.x];
        sbet[threadIdx.x] = bb[threadIdx.x];
    }

    float acc[4][4][4];
#pragma unroll
    for (int a = 0; a < 4; a++)
#pragma unroll
        for (int b = 0; b < 4; b++)
#pragma unroll
            for (int cc = 0; cc < 4; cc++) acc[a][b][cc] = 0.f;

    gemm_ml(acc, g_xhi, g_xlo, g_wqkvhi, m0, n0, sa);

    float* Dst = (float*)(smc + 1024);
    const int wid = threadIdx.x >> 5, lane = threadIdx.x & 31;
    const int wm = wid & 1, wn = wid >> 1;
    const int r = lane >> 2, c4 = lane & 3;
#pragma unroll
    for (int mf = 0; mf < 4; mf++)
#pragma unroll
        for (int nf = 0; nf < 4; nf++) {
            const int m = wm * 64 + mf * 16 + r;
            const int n = wn * 32 + nf * 8 + c4 * 2;
            *(float2*)&Dst[m * DPITCH + n]       = make_float2(acc[mf][nf][0], acc[mf][nf][1]);
            *(float2*)&Dst[(m + 8) * DPITCH + n] = make_float2(acc[mf][nf][2], acc[mf][nf][3]);
        }
    __syncthreads();

    const int m = threadIdx.x >> 1, hc = threadIdx.x & 1;
    const float* rowp = Dst + m * DPITCH + hc * 64;
    float f[64];
#pragma unroll
    for (int i = 0; i < 64; i++) f[i] = rowp[i];
    const int bidx = m0 >> 11, nq = (m0 & 2047) + m;
    const int h = ((n0 & 1023) >> 6) + hc;
    const size_t base = (((size_t)(bidx * H_ + h)) * N_ + nq) * D_;
    if (s < 2) {
        float sum = 0.f;
#pragma unroll
        for (int i = 0; i < 64; i++) sum += f[i];
        float mu = sum * (1.0f / 64.0f);
        float vs = 0.f;
#pragma unroll
        for (int i = 0; i < 64; i++) { float d = f[i] - mu; vs += d * d; }
        float rs = rsqrtf(vs * (1.0f / 64.0f) + 1e-5f);
#pragma unroll
        for (int i = 0; i < 64; i++) f[i] = (f[i] - mu) * rs * sgam[i] + sbet[i];
        if (s == 0) {
#pragma unroll
            for (int i = 0; i < 64; i += 2) {
                uint32_t hp, lp;
                split2h(f[i], f[i + 1], hp, lp);
                *(uint32_t*)(g_qhi + base + i) = hp;
                *(uint32_t*)(g_qlo + base + i) = lp;
            }
        } else {
#pragma unroll
            for (int i = 0; i < 64; i += 2)
                *(uint32_t*)(g_khi + base + i) = pack_hi2(f[i], f[i + 1]);
        }
    } else {
#pragma unroll
        for (int i = 0; i < 64; i += 4)
            *(float4*)&g_v[base + i] = make_float4(f[i], f[i + 1], f[i + 2], f[i + 3]);
    }
}

// ---------------------------------------------------------------------------
// V transpose:  g_v[b,h,key,d] (fp32) -> g_vthi[b,h,d,key] (fp16)
// ---------------------------------------------------------------------------
__global__ __launch_bounds__(256) void vt_kernel() {
    __shared__ float tile[64][65];
    const int kt = blockIdx.x, bh = blockIdx.y;
    const int tid = threadIdx.x;
    const float* src = g_v + (size_t)bh * N_ * D_ + (size_t)(kt * 64) * D_;
#pragma unroll
    for (int j = 0; j < 4; j++) {
        int id = tid + j * 256;
        int row = id >> 4, c4i = (id & 15) * 4;
        float4 v = *(const float4*)(src + row * D_ + c4i);
        tile[row][c4i] = v.x; tile[row][c4i + 1] = v.y;
        tile[row][c4i + 2] = v.z; tile[row][c4i + 3] = v.w;
    }
    __syncthreads();
    const int d = tid >> 2, kg = (tid & 3) * 16;
    h16* dh = g_vthi + (size_t)bh * D_ * N_ + (size_t)d * N_ + kt * 64 + kg;
#pragma unroll
    for (int i = 0; i < 16; i += 2)
        *(uint32_t*)(dh + i) = pack_hi2(tile[kg + i][d], tile[kg + i + 1][d]);
}

// ---------------------------------------------------------------------------
// Flash attention, fp16 2-pass: S = (Qhi+Qlo)·Kh,  O += (Phi+Plo)·Vh.
// 128 threads = 4 warps; warp = 32 q-rows (2 m-frags); Bc = 64 keys/iter.
// ---------------------------------------------------------------------------
#define FP 72
#define KT (64 * FP)        // 4608 halves per array
#define QREG (128 * FP)     // 9216 halves
#define SMEM_FLASH ((QREG + 4 * KT) * 2)   // 55296 bytes

__global__ __launch_bounds__(128) void flash_mma_kernel(const unsigned char* __restrict__ mask) {
    extern __shared__ char smc[];
    h16* sh = (h16*)smc;
    const uint32_t shb = smem_u32(sh);

    const int qt = blockIdx.x, h = blockIdx.y, b = blockIdx.z;
    const int tid = threadIdx.x, wid = tid >> 5, lane = tid & 31;
    const int r = lane >> 2, c4 = lane & 3;
    const int wrow = wid * 32;
    const size_t qkoff = ((size_t)(b * H_ + h)) * N_ * D_;
    const size_t vtoff = ((size_t)(b * H_ + h)) * D_ * N_;

    const uint32_t qhi_base = (uint32_t)(QREG + 2 * KT);   // buf1 area (halves)

    // ---- stage Q: hi -> buf1 (transient), lo -> resident ----
    {
        const h16* qh = g_qhi + qkoff + (size_t)(qt * 128) * D_;
        const h16* ql = g_qlo + qkoff + (size_t)(qt * 128) * D_;
#pragma unroll
        for (int j = 0; j < 8; j++) {
            int id = tid + j * 128;
            int row = id >> 3, c8 = (id & 7) * 8;
            CP16(shb + (qhi_base + row * FP + c8) * 2, qh + row * D_ + c8);
            CP16(shb + (row * FP + c8) * 2,            ql + row * D_ + c8);
        }
        CP_COMMIT();
    }

    auto issue_tile = [&](int kt2, int buf) {
        const uint32_t bo = (uint32_t)(QREG + buf * 2 * KT) * 2;
        const h16* kh = g_khi + qkoff + (size_t)(kt2 * 64) * D_;
        const h16* vh = g_vthi + vtoff + kt2 * 64;
#pragma unroll
        for (int j = 0; j < 4; j++) {
            int id = tid + j * 128;
            int row = id >> 3, c8 = (id & 7) * 8;
            uint32_t sd = bo + (row * FP + c8) * 2;
            CP16(shb + sd,          kh + row * D_ + c8);
            CP16(shb + sd + KT * 2, vh + (size_t)row * N_ + c8);
        }
        CP_COMMIT();
    };
    issue_tile(0, 0);   // buf0 — does not overlap Q-hi staging (buf1)
    CP_WAIT0();
    __syncthreads();

    // ---- Q-hi fragments to registers (2 m-frags x 4 k-chunks) ----
    uint32_t aQh[2][4][4];
#pragma unroll
    for (int mf = 0; mf < 2; mf++)
#pragma unroll
        for (int kc = 0; kc < 4; kc++) {
            const int ba = qhi_base + (wrow + mf * 16 + r) * FP + kc * 16 + c4 * 2;
            aQh[mf][kc][0] = *(const uint32_t*)(sh + ba);
            aQh[mf][kc][1] = *(const uint32_t*)(sh + ba + 8 * FP);
            aQh[mf][kc][2] = *(const uint32_t*)(sh + ba + 8);
            aQh[mf][kc][3] = *(const uint32_t*)(sh + ba + 8 * FP + 8);
        }
    __syncthreads();   // all warps done with Q-hi before buf1 is reused

    float of[2][8][4];
#pragma unroll
    for (int mf = 0; mf < 2; mf++)
#pragma unroll
        for (int nb = 0; nb < 8; nb++)
#pragma unroll
            for (int k = 0; k < 4; k++) of[mf][nb][k] = 0.f;
    float mI[2][2], lI[2][2];
#pragma unroll
    for (int mf = 0; mf < 2; mf++) {
        mI[mf][0] = mI[mf][1] = -FLT_MAX;
        lI[mf][0] = lI[mf][1] = 0.f;
    }

    const unsigned char* mb[2];
    mb[0] = mask + ((size_t)b * N_ + qt * 128 + wrow + r) * N_;
    mb[1] = mb[0] + 16 * (size_t)N_;
    const float scale = 0.125f;

    for (int kt2 = 0; kt2 < N_ / 64; kt2++) {
        if (kt2 < N_ / 64 - 1) issue_tile(kt2 + 1, (kt2 + 1) & 1);

        const h16* sKh = sh + QREG + (kt2 & 1) * 2 * KT;
        const h16* sVh = sKh + KT;

        // ---- S = (Qhi + Qlo) Kh ----
        float sf[2][8][4];
#pragma unroll
        for (int mf = 0; mf < 2; mf++)
#pragma unroll
            for (int nb = 0; nb < 8; nb++)
                sf[mf][nb][0] = sf[mf][nb][1] = sf[mf][nb][2] = sf[mf][nb][3] = 0.f;

#pragma unroll
        for (int kc = 0; kc < 4; kc++) {
            uint32_t ql[2][4];
#pragma unroll
            for (int mf = 0; mf < 2; mf++) {
                const int ba = (wrow + mf * 16 + r) * FP + kc * 16 + c4 * 2;
                ql[mf][0] = *(const uint32_t*)(sh + ba);
                ql[mf][1] = *(const uint32_t*)(sh + ba + 8 * FP);
                ql[mf][2] = *(const uint32_t*)(sh + ba + 8);
                ql[mf][3] = *(const uint32_t*)(sh + ba + 8 * FP + 8);
            }
#pragma unroll
            for (int g = 0; g < 2; g++) {
                uint32_t kh0[4], kh1[4];
#pragma unroll
                for (int j = 0; j < 4; j++) {
                    const int kb = ((g * 4 + j) * 8 + r) * FP + kc * 16 + c4 * 2;
                    kh0[j] = *(const uint32_t*)(sKh + kb);
                    kh1[j] = *(const uint32_t*)(sKh + kb + 8);
                }
#pragma unroll
                for (int mf = 0; mf < 2; mf++) {
#pragma unroll
                    for (int j = 0; j < 4; j++)
                        mma_f16(sf[mf][g * 4 + j], aQh[mf][kc][0], aQh[mf][kc][1],
                                aQh[mf][kc][2], aQh[mf][kc][3], kh0[j], kh1[j]);
#pragma unroll
                    for (int j = 0; j < 4; j++)
                        mma_f16(sf[mf][g * 4 + j], ql[mf][0], ql[mf][1],
                                ql[mf][2], ql[mf][3], kh0[j], kh1[j]);
                }
            }
        }

        // ---- scale + mask + online softmax ----
#pragma unroll
        for (int mf = 0; mf < 2; mf++) {
            const unsigned char* mr0 = mb[mf] + kt2 * 64 + c4 * 2;
#pragma unroll
            for (int nb = 0; nb < 8; nb++) {
                uchar2 k0 = *(const uchar2*)(mr0 + nb * 8);
                uchar2 k8 = *(const uchar2*)(mr0 + 8 * N_ + nb * 8);
                sf[mf][nb][0] = k0.x ? -FLT_MAX : sf[mf][nb][0] * scale;
                sf[mf][nb][1] = k0.y ? -FLT_MAX : sf[mf][nb][1] * scale;
                sf[mf][nb][2] = k8.x ? -FLT_MAX : sf[mf][nb][2] * scale;
                sf[mf][nb][3] = k8.y ? -FLT_MAX : sf[mf][nb][3] * scale;
            }
            float mx0 = -FLT_MAX, mx1 = -FLT_MAX;
#pragma unroll
            for (int nb = 0; nb < 8; nb++) {
                mx0 = fmaxf(mx0, fmaxf(sf[mf][nb][0], sf[mf][nb][1]));
                mx1 = fmaxf(mx1, fmaxf(sf[mf][nb][2], sf[mf][nb][3]));
            }
            mx0 = fmaxf(mx0, __shfl_xor_sync(0xffffffffu, mx0, 1));
            mx0 = fmaxf(mx0, __shfl_xor_sync(0xffffffffu, mx0, 2));
            mx1 = fmaxf(mx1, __shfl_xor_sync(0xffffffffu, mx1, 1));
            mx1 = fmaxf(mx1, __shfl_xor_sync(0xffffffffu, mx1, 2));
            const float mn0 = fmaxf(mI[mf][0], mx0), mn1 = fmaxf(mI[mf][1], mx1);
            const float cor0 = __expf(mI[mf][0] - mn0), cor1 = __expf(mI[mf][1] - mn1);
            mI[mf][0] = mn0; mI[mf][1] = mn1;
            float rs0 = 0.f, rs1 = 0.f;
#pragma unroll
            for (int nb = 0; nb < 8; nb++) {
                sf[mf][nb][0] = __expf(sf[mf][nb][0] - mn0);
                sf[mf][nb][1] = __expf(sf[mf][nb][1] - mn0);
                sf[mf][nb][2] = __expf(sf[mf][nb][2] - mn1);
                sf[mf][nb][3] = __expf(sf[mf][nb][3] - mn1);
                rs0 += sf[mf][nb][0] + sf[mf][nb][1];
                rs1 += sf[mf][nb][2] + sf[mf][nb][3];
            }
            rs0 += __shfl_xor_sync(0xffffffffu, rs0, 1);
            rs0 += __shfl_xor_sync(0xffffffffu, rs0, 2);
            rs1 += __shfl_xor_sync(0xffffffffu, rs1, 1);
            rs1 += __shfl_xor_sync(0xffffffffu, rs1, 2);
            lI[mf][0] = lI[mf][0] * cor0 + rs0;
            lI[mf][1] = lI[mf][1] * cor1 + rs1;
#pragma unroll
            for (int nb = 0; nb < 8; nb++) {
                of[mf][nb][0] *= cor0; of[mf][nb][1] *= cor0;
                of[mf][nb][2] *= cor1; of[mf][nb][3] *= cor1;
            }
        }

        // ---- O += (Phi + Plo) Vh ----
#pragma unroll
        for (int kc = 0; kc < 4; kc++) {
            uint32_t ph[2][4], pl[2][4];
#pragma unroll
            for (int mf = 0; mf < 2; mf++) {
                split2h(sf[mf][2 * kc][0], sf[mf][2 * kc][1], ph[mf][0], pl[mf][0]);
                split2h(sf[mf][2 * kc][2], sf[mf][2 * kc][3], ph[mf][1], pl[mf][1]);
                split2h(sf[mf][2 * kc + 1][0], sf[mf][2 * kc + 1][1], ph[mf][2], pl[mf][2]);
                split2h(sf[mf][2 * kc + 1][2], sf[mf][2 * kc + 1][3], ph[mf][3], pl[mf][3]);
            }
#pragma unroll
            for (int g = 0; g < 2; g++) {
                uint32_t vh0[4], vh1[4];
#pragma unroll
                for (int j = 0; j < 4; j++) {
                    const int vb = ((g * 4 + j) * 8 + r) * FP + kc * 16 + c4 * 2;
                    vh0[j] = *(const uint32_t*)(sVh + vb);
                    vh1[j] = *(const uint32_t*)(sVh + vb + 8);
                }
#pragma unroll
                for (int mf = 0; mf < 2; mf++) {
#pragma unroll
                    for (int j = 0; j < 4; j++)
                        mma_f16(of[mf][g * 4 + j], ph[mf][0], ph[mf][1], ph[mf][2], ph[mf][3],
                                vh0[j], vh1[j]);
#pragma unroll
                    for (int j = 0; j < 4; j++)
                        mma_f16(of[mf][g * 4 + j], pl[mf][0], pl[mf][1], pl[mf][2], pl[mf][3],
                                vh0[j], vh1[j]);
                }
            }
        }

        if (kt2 < N_ / 64 - 1) CP_WAIT0();
        __syncthreads();
    }

    // ---- epilogue: normalize, write split fp16 att [B,N,C] ----
#pragma unroll
    for (int mf = 0; mf < 2; mf++) {
        const float inv0 = 1.0f / lI[mf][0], inv1 = 1.0f / lI[mf][1];
        const int row0 = qt * 128 + wrow + mf * 16 + r;
        const size_t ob0 = ((size_t)b * N_ + row0) * C_ + h * 64 + c4 * 2;
        const size_t ob1 = ob0 + 8 * (size_t)C_;
#pragma unroll
        for (int nb = 0; nb < 8; nb++) {
            uint32_t hp, lp;
            split2h(of[mf][nb][0] * inv0, of[mf][nb][1] * inv0, hp, lp);
            *(uint32_t*)(g_atthi + ob0 + nb * 8) = hp;
            *(uint32_t*)(g_attlo + ob0 + nb * 8) = lp;
            split2h(of[mf][nb][2] * inv1, of[mf][nb][3] * inv1, hp, lp);
            *(uint32_t*)(g_atthi + ob1 + nb * 8) = hp;
            *(uint32_t*)(g_attlo + ob1 + nb * 8) = lp;
        }
    }
}

// ---------------------------------------------------------------------------
// Projection GEMM + bias. grid (8, 32), 256 threads.
// ---------------------------------------------------------------------------
__global__ __launch_bounds__(256) void proj_mma_kernel(const float* __restrict__ bias,
                                                       float* __restrict__ out) {
    extern __shared__ char smc[];
    float* sbias = (float*)smc;
    h16* sa = (h16*)(smc + 1024);
    const int n0 = blockIdx.x * 128, m0 = blockIdx.y * 128;
    if (threadIdx.x < 128) sbias[threadIdx.x] = bias[n0 + threadIdx.x];

    float acc[4][4][4];
#pragma unroll
    for (int a = 0; a < 4; a++)
#pragma unroll
        for (int b = 0; b < 4; b++)
#pragma unroll
            for (int cc = 0; cc < 4; cc++) acc[a][b][cc] = 0.f;

    gemm_ml(acc, g_atthi, g_attlo, g_wprojhi, m0, n0, sa);

    const int wid = threadIdx.x >> 5, lane = threadIdx.x & 31;
    const int wm = wid & 1, wn = wid >> 1;
    const int r = lane >> 2, c4 = lane & 3;
#pragma unroll
    for (int mf = 0; mf < 4; mf++)
#pragma unroll
        for (int nf = 0; nf < 4; nf++) {
            const int m = wm * 64 + mf * 16 + r;
            const int n = wn * 32 + nf * 8 + c4 * 2;
            const float b0 = sbias[n], b1 = sbias[n + 1];
            *(float2*)&out[(size_t)(m0 + m) * C_ + n0 + n] =
                make_float2(acc[mf][nf][0] + b0, acc[mf][nf][1] + b1);
            *(float2*)&out[(size_t)(m0 + m + 8) * C_ + n0 + n] =
                make_float2(acc[mf][nf][2] + b0, acc[mf][nf][3] + b1);
        }
}

// ---------------------------------------------------------------------------
extern "C" void kernel_launch(void* const* d_in, const int* in_sizes, int n_in,
                              void* d_out, int out_size) {
    const float*         x      = (const float*)d_in[0];
    const unsigned char* mask   = (const unsigned char*)d_in[1];
    const float*         w_qkv  = (const float*)d_in[2];
    const float*         w_proj = (const float*)d_in[3];
    const float*         b_proj = (const float*)d_in[4];
    const float*         qg     = (const float*)d_in[5];
    const float*         qb     = (const float*)d_in[6];
    const float*         kg     = (const float*)d_in[7];
    const float*         kb     = (const float*)d_in[8];
    float* out = (float*)d_out;

    conv_kernel<<<4096, 256>>>(x, 0, (B_ * N_ * C_) / 4);
    conv_kernel<<<3072, 256>>>(w_qkv, 1, (3 * C_ * C_) / 4);
    conv_kernel<<<1024, 256>>>(w_proj, 2, (C_ * C_) / 4);

    cudaFuncSetAttribute(qkv_mma_kernel, cudaFuncAttributeMaxDynamicSharedMemorySize, SMEM_GEMM);
    qkv_mma_kernel<<<dim3(24, 32), 256, SMEM_GEMM>>>(qg, qb, kg, kb);

    vt_kernel<<<dim3(N_ / 64, B_ * H_), 256>>>();

    cudaFuncSetAttribute(flash_mma_kernel, cudaFuncAttributeMaxDynamicSharedMemorySize, SMEM_FLASH);
    flash_mma_kernel<<<dim3(N_ / 128, H_, B_), 128, SMEM_FLASH>>>(mask);

    cudaFuncSetAttribute(proj_mma_kernel, cudaFuncAttributeMaxDynamicSharedMemorySize, SMEM_GEMM);
    proj_mma_kernel<<<dim3(8, 32), 256, SMEM_GEMM>>>(b_proj, out);
}